// round 7
// baseline (speedup 1.0000x reference)
#include <cuda_runtime.h>
#include <cuda_fp16.h>
#include <math.h>
#include <stdint.h>

// ===========================================================================
// Live math (softmax over size-1 axis == 1 kills q/Wq/bq/rpb/k-half of Wkv):
//   h = LN(x;g1,b1); v = h@Wv+bv; y = v@Wp+bp;
//   z = y + gelu(LN(y;g2,b2)@W1+bm1)@W2 + bm2
// mma.sync m16n8k16 fp16 (fp32 accum), ldmatrix, single-shot K=128 B tiles
// with cross-phase cp.async prefetch.  64 tokens/CTA, 8 warps, 2 CTAs/SM.
// R7: 1-MUFU gelu (A&S 7.1.28), hoisted B-load addressing.
// ===========================================================================

#define CC    384
#define DD    128
#define HIDN  512
#define MT    64
#define NTHR  256
#define EPSV  1e-5f

#define BSTR  72     // K=64 chunk stride (halves); row step 144B -> ldsm-clean
#define WSTR  136    // K=128 tile stride (halves); row step 272B -> ldsm-clean
#define VSTR  136
#define YSTR  132

// smem byte offsets
#define OFF_BB   0                    // B region: max(2x128x72, 128x136)x2 = 36864
#define OFF_VB   36864                // v / lny : 64 x 136 fp16 = 17408
#define OFF_GB   54272                // gelu    : 64 x 136 fp16 (A-chunk aliases)
#define OFF_YB   71680                // y       : 64 x 132 fp32 = 33792
#define OFF_MEAN 105472
#define OFF_RSTD 105728
#define SMEM_BYTES 105984

// Pre-transposed fp16 weights, [n][k] row-major (mma row.col B operand)
__device__ __half g_WvT[DD * CC];
__device__ __half g_WpT[DD * DD];
__device__ __half g_W1T[HIDN * DD];
__device__ __half g_W2T[DD * HIDN];

__device__ __forceinline__ uint32_t smem_u32(const void* p) {
    uint32_t a;
    asm("{ .reg .u64 t; cvta.to.shared.u64 t, %1; cvt.u32.u64 %0, t; }"
        : "=r"(a) : "l"(p));
    return a;
}
__device__ __forceinline__ void cp16(uint32_t dst, const void* src) {
    asm volatile("cp.async.cg.shared.global [%0], [%1], 16;"
                 :: "r"(dst), "l"(src));
}
__device__ __forceinline__ void cp_commit() {
    asm volatile("cp.async.commit_group;" ::: "memory");
}
template<int N> __device__ __forceinline__ void cp_wait() {
    asm volatile("cp.async.wait_group %0;" :: "n"(N) : "memory");
}
__device__ __forceinline__ void ldsm4(uint32_t r[4], uint32_t addr) {
    asm volatile("ldmatrix.sync.aligned.m8n8.x4.shared.b16 {%0,%1,%2,%3}, [%4];"
                 : "=r"(r[0]), "=r"(r[1]), "=r"(r[2]), "=r"(r[3]) : "r"(addr));
}
__device__ __forceinline__ void mma16(float c[4],
    uint32_t a0, uint32_t a1, uint32_t a2, uint32_t a3,
    uint32_t b0, uint32_t b1) {
    asm volatile(
        "mma.sync.aligned.m16n8k16.row.col.f32.f16.f16.f32 "
        "{%0,%1,%2,%3}, {%4,%5,%6,%7}, {%8,%9}, {%0,%1,%2,%3};"
        : "+f"(c[0]), "+f"(c[1]), "+f"(c[2]), "+f"(c[3])
        : "r"(a0), "r"(a1), "r"(a2), "r"(a3), "r"(b0), "r"(b1));
}

// Gelu with exact erf via A&S 7.1.28: erf(x) = 1 - (1+a1 x+...+a6 x^6)^-16.
// Abs err ~2e-5 (<< fp16 operand rounding). ONE MUFU (rcp), rest FMA/mul.
__device__ __forceinline__ float gelu_f(float v) {
    float x = fabsf(v) * 0.70710678118654752f;
    float d = fmaf(x, 0.0000430638f, 0.0002765672f);
    d = fmaf(d, x, 0.0001520143f);
    d = fmaf(d, x, 0.0092705272f);
    d = fmaf(d, x, 0.0422820123f);
    d = fmaf(d, x, 0.0705230784f);
    d = fmaf(d, x, 1.0f);
    float r = __frcp_rn(d);          // MUFU.RCP
    float r2  = r * r;
    float r4  = r2 * r2;
    float r8  = r4 * r4;
    float r16 = r8 * r8;
    float er  = 1.f - r16;           // erf(|x|)
    return 0.5f * v * (1.f + copysignf(er, v));
}

// ----- MMA bodies ---------------------------------------------------------
#define MMA_KSTEP(acc, aA0, aA1, aB0, aB1, koff) { \
    uint32_t a0[4], a1[4], b0[4], b1[4]; \
    ldsm4(a0, (aA0) + (koff)); ldsm4(a1, (aA1) + (koff)); \
    ldsm4(b0, (aB0) + (koff)); ldsm4(b1, (aB1) + (koff)); \
    mma16(acc[0][0], a0[0],a0[1],a0[2],a0[3], b0[0], b0[2]); \
    mma16(acc[0][1], a0[0],a0[1],a0[2],a0[3], b0[1], b0[3]); \
    mma16(acc[0][2], a0[0],a0[1],a0[2],a0[3], b1[0], b1[2]); \
    mma16(acc[0][3], a0[0],a0[1],a0[2],a0[3], b1[1], b1[3]); \
    mma16(acc[1][0], a1[0],a1[1],a1[2],a1[3], b0[0], b0[2]); \
    mma16(acc[1][1], a1[0],a1[1],a1[2],a1[3], b0[1], b0[3]); \
    mma16(acc[1][2], a1[0],a1[1],a1[2],a1[3], b1[0], b1[2]); \
    mma16(acc[1][3], a1[0],a1[1],a1[2],a1[3], b1[1], b1[3]); \
}

// K=64 chunk (stage 2): A stride lda, B stride BSTR
__device__ __forceinline__ void mma_chunk64(
    const __half* As, int lda, const __half* Bs,
    float acc[2][4][4], int wm, int wn, int lane)
{
    const int lrow = lane & 15;
    const int lcol = (lane >> 4) << 3;
    uint32_t aA0 = smem_u32(As + (wm * 32 +      lrow) * lda + lcol);
    uint32_t aA1 = smem_u32(As + (wm * 32 + 16 + lrow) * lda + lcol);
    uint32_t aB0 = smem_u32(Bs + (wn * 32 +      lrow) * BSTR + lcol);
    uint32_t aB1 = smem_u32(Bs + (wn * 32 + 16 + lrow) * BSTR + lcol);
    #pragma unroll
    for (int k0 = 0; k0 < 64; k0 += 16)
        MMA_KSTEP(acc, aA0, aA1, aB0, aB1, k0 * 2);
}

// K=128 GEMM: A stride VSTR, B stride WSTR (single tile)
__device__ __forceinline__ void mma_gemm128(
    const __half* As, const __half* Bs,
    float acc[2][4][4], int wm, int wn, int lane)
{
    const int lrow = lane & 15;
    const int lcol = (lane >> 4) << 3;
    uint32_t aA0 = smem_u32(As + (wm * 32 +      lrow) * VSTR + lcol);
    uint32_t aA1 = smem_u32(As + (wm * 32 + 16 + lrow) * VSTR + lcol);
    uint32_t aB0 = smem_u32(Bs + (wn * 32 +      lrow) * WSTR + lcol);
    uint32_t aB1 = smem_u32(Bs + (wn * 32 + 16 + lrow) * WSTR + lcol);
    #pragma unroll
    for (int k0 = 0; k0 < 128; k0 += 16)
        MMA_KSTEP(acc, aA0, aA1, aB0, aB1, k0 * 2);
}

#define ZERO_ACC(A) { _Pragma("unroll") for (int _m=0;_m<2;_m++) \
    _Pragma("unroll") for (int _n=0;_n<4;_n++) \
    _Pragma("unroll") for (int _q=0;_q<4;_q++) (A)[_m][_n][_q] = 0.f; }

// --------------------------- weight prep kernel ---------------------------
__global__ void prep_kernel(const float* __restrict__ Wkv,
                            const float* __restrict__ Wp,
                            const float* __restrict__ W1,
                            const float* __restrict__ W2) {
    int tid = blockIdx.x * blockDim.x + threadIdx.x;
    int str = gridDim.x * blockDim.x;
    for (int s = tid; s < CC * DD; s += str) {
        int k = s / DD, n = s % DD;
        g_WvT[n * CC + k] = __float2half_rn(Wkv[k * 256 + 128 + n]);
    }
    for (int s = tid; s < DD * DD; s += str) {
        int k = s / DD, n = s % DD;
        g_WpT[n * DD + k] = __float2half_rn(Wp[k * DD + n]);
    }
    for (int s = tid; s < DD * HIDN; s += str) {
        int k = s / HIDN, n = s % HIDN;
        g_W1T[n * DD + k] = __float2half_rn(W1[k * HIDN + n]);
    }
    for (int s = tid; s < HIDN * DD; s += str) {
        int k = s / DD, n = s % DD;
        g_W2T[n * HIDN + k] = __float2half_rn(W2[k * DD + n]);
    }
}

// ------------------------------ main kernel -------------------------------
extern __shared__ char smem_raw[];

__global__ void __launch_bounds__(NTHR, 2) fused_mma(
    const float* __restrict__ x,
    const float* __restrict__ g1, const float* __restrict__ b1,
    const float* __restrict__ bkv, const float* __restrict__ bp,
    const float* __restrict__ g2, const float* __restrict__ b2,
    const float* __restrict__ bm1, const float* __restrict__ bm2,
    float* __restrict__ out)
{
    __half* Bb0 = (__half*)(smem_raw + OFF_BB);
    __half* Bb1 = Bb0 + 128 * BSTR;
    __half* Bw  = Bb0;                           // K=128 tile (same region)
    __half* Vb  = (__half*)(smem_raw + OFF_VB);
    __half* Gb  = (__half*)(smem_raw + OFF_GB);
    __half* Ab  = (__half*)(smem_raw + OFF_GB);  // alias: stage-2 only
    float*  Yb  = (float*)(smem_raw + OFF_YB);
    float* smean = (float*)(smem_raw + OFF_MEAN);
    float* srstd = (float*)(smem_raw + OFF_RSTD);

    const int tid  = threadIdx.x;
    const int lane = tid & 31;
    const int warp = tid >> 5;
    const int wm   = warp >> 2;      // 0..1 (M tile)
    const int wn   = warp & 3;       // 0..3 (N tile)
    const int gid  = lane >> 2;      // 0..7
    const int tig  = lane & 3;       // 0..3
    const long tile0 = (long)blockIdx.x * MT;

    // Hoisted B-load geometry (reused by every issue below)
    const int brow64 = tid >> 3,  bcol64 = (tid & 7) << 3;    // K=64 layout
    const int brow128 = tid >> 4, bcol128 = (tid & 15) << 3;  // K=128 layout
    uint32_t bdst64[4], bdst128[8];
    #pragma unroll
    for (int i = 0; i < 4; i++)
        bdst64[i] = smem_u32(Bb0 + (brow64 + 32 * i) * BSTR + bcol64);
    #pragma unroll
    for (int i = 0; i < 8; i++)
        bdst128[i] = smem_u32(Bw + (brow128 + 16 * i) * WSTR + bcol128);
    const uint32_t b64_delta = (uint32_t)(128 * BSTR * 2);   // Bb0 -> Bb1 bytes

    // issue helpers (lambdas capture hoisted addresses)
    auto issueB64 = [&](int buf, const __half* Wg, int ldw, int kc) {
        const __half* src = Wg + brow64 * ldw + kc + bcol64;
        uint32_t add = buf ? b64_delta : 0u;
        #pragma unroll
        for (int i = 0; i < 4; i++)
            cp16(bdst64[i] + add, src + 32 * i * ldw);
    };
    auto issueB128 = [&](const __half* Wg, int ldw) {
        const __half* src = Wg + brow128 * ldw + bcol128;
        #pragma unroll
        for (int i = 0; i < 8; i++)
            cp16(bdst128[i], src + 16 * i * ldw);
    };

    // Prefetch first Wv B-chunk: hides under LN stats.
    issueB64(0, g_WvT, CC, 0); cp_commit();

    // ---------------- LN(x) stats (8 rows per warp) ----------------
    #pragma unroll 1
    for (int i = 0; i < 8; i++) {
        int row = warp * 8 + i;
        const float* xr = x + (tile0 + row) * CC;
        float s = 0.f, ss = 0.f;
        #pragma unroll
        for (int u = 0; u < 12; u++) {
            float t = xr[lane + 32 * u];
            s += t; ss += t * t;
        }
        #pragma unroll
        for (int o = 16; o > 0; o >>= 1) {
            s  += __shfl_xor_sync(0xffffffffu, s,  o);
            ss += __shfl_xor_sync(0xffffffffu, ss, o);
        }
        if (lane == 0) {
            float m = s * (1.f / 384.f);
            float v = ss * (1.f / 384.f) - m * m;
            smean[row] = m;
            srstd[row] = rsqrtf(v + EPSV);
        }
    }
    __syncthreads();

    // ---------------- v = LN(x) @ WvT  (K=384, 6 x K=64 chunks) -----------
    float vacc[2][4][4];
    ZERO_ACC(vacc);
    #pragma unroll 1
    for (int c = 0; c < 6; c++) {
        __half* Bcur = (c & 1) ? Bb1 : Bb0;
        if (c < 5) {
            issueB64(!(c & 1), g_WvT, CC, (c + 1) * 64);
            cp_commit();
        }
        // fill A chunk: normalize x[:, kc..kc+63] -> fp16 (float4 loads)
        int kc = c * 64;
        #pragma unroll
        for (int i = 0; i < 4; i++) {
            int idx = tid + NTHR * i;            // 64 rows x 16 quads
            int row = idx >> 4, q = (idx & 15) * 4;
            int k = kc + q;
            float4 xx = *(const float4*)(x + (tile0 + row) * CC + k);
            float4 gg = *(const float4*)(g1 + k);
            float4 bb = *(const float4*)(b1 + k);
            float m = smean[row], rs = srstd[row];
            __half2 h0 = __floats2half2_rn(fmaf((xx.x - m) * rs, gg.x, bb.x),
                                           fmaf((xx.y - m) * rs, gg.y, bb.y));
            __half2 h1 = __floats2half2_rn(fmaf((xx.z - m) * rs, gg.z, bb.z),
                                           fmaf((xx.w - m) * rs, gg.w, bb.w));
            uint2 pk = make_uint2(*(uint32_t*)&h0, *(uint32_t*)&h1);
            *(uint2*)(Ab + row * BSTR + q) = pk;
        }
        if (c < 5) cp_wait<1>(); else cp_wait<0>();
        __syncthreads();
        mma_chunk64(Ab, BSTR, Bcur, vacc, wm, wn, lane);
        __syncthreads();
    }

    // Prefetch full Wp tile: hides under v epilogue.
    issueB128(g_WpT, DD); cp_commit();

    // v epilogue -> Vb (fp16)
    #pragma unroll
    for (int mi = 0; mi < 2; mi++)
        #pragma unroll
        for (int ni = 0; ni < 4; ni++) {
            int r0 = wm * 32 + mi * 16 + gid;
            int cb = wn * 32 + ni * 8 + tig * 2;
            float b0 = bkv[128 + cb], b1v = bkv[129 + cb];
            *(__half2*)(Vb + r0 * VSTR + cb) =
                __floats2half2_rn(vacc[mi][ni][0] + b0, vacc[mi][ni][1] + b1v);
            *(__half2*)(Vb + (r0 + 8) * VSTR + cb) =
                __floats2half2_rn(vacc[mi][ni][2] + b0, vacc[mi][ni][3] + b1v);
        }

    // ---------------- y = v @ WpT (K=128, single tile) ----------------
    float yacc[2][4][4];
    ZERO_ACC(yacc);
    cp_wait<0>();
    __syncthreads();                 // Wp ready; Vb published
    mma_gemm128(Vb, Bw, yacc, wm, wn, lane);
    __syncthreads();

    // Prefetch W1 tile0: hides under y epilogue + LN(y).
    issueB128(g_W1T, DD); cp_commit();

    // y epilogue -> Yb (fp32)
    #pragma unroll
    for (int mi = 0; mi < 2; mi++)
        #pragma unroll
        for (int ni = 0; ni < 4; ni++) {
            int r0 = wm * 32 + mi * 16 + gid;
            int cb = wn * 32 + ni * 8 + tig * 2;
            Yb[r0 * YSTR + cb]         = yacc[mi][ni][0] + bp[cb];
            Yb[r0 * YSTR + cb + 1]     = yacc[mi][ni][1] + bp[cb + 1];
            Yb[(r0 + 8) * YSTR + cb]   = yacc[mi][ni][2] + bp[cb];
            Yb[(r0 + 8) * YSTR + cb+1] = yacc[mi][ni][3] + bp[cb + 1];
        }
    __syncthreads();                 // publish Yb

    // lny = LN(y) -> Vb (fp16)
    #pragma unroll 1
    for (int i = 0; i < 8; i++) {
        int row = warp * 8 + i;
        float vals[4];
        float s = 0.f, ss = 0.f;
        #pragma unroll
        for (int u = 0; u < 4; u++) {
            float t = Yb[row * YSTR + lane + 32 * u];
            vals[u] = t; s += t; ss += t * t;
        }
        #pragma unroll
        for (int o = 16; o > 0; o >>= 1) {
            s  += __shfl_xor_sync(0xffffffffu, s,  o);
            ss += __shfl_xor_sync(0xffffffffu, ss, o);
        }
        float m  = s * (1.f / 128.f);
        float vv = ss * (1.f / 128.f) - m * m;
        float rs = rsqrtf(vv + EPSV);
        #pragma unroll
        for (int u = 0; u < 4; u++) {
            int k = lane + 32 * u;
            Vb[row * VSTR + k] =
                __float2half_rn((vals[u] - m) * rs * g2[k] + b2[k]);
        }
    }

    // ---------------- MLP: 4 hidden tiles of 128 ----------------
    float uacc[2][4][4];
    ZERO_ACC(uacc);
    #pragma unroll 1
    for (int cc = 0; cc < 4; cc++) {
        cp_wait<0>();
        __syncthreads();             // W1(cc) ready; lny/Gb published
        float tacc[2][4][4];
        ZERO_ACC(tacc);
        mma_gemm128(Vb, Bw, tacc, wm, wn, lane);
        __syncthreads();

        issueB128(g_W2T + cc * 128, HIDN); cp_commit();

        // gelu epilogue -> Gb (fp16)
        #pragma unroll
        for (int mi = 0; mi < 2; mi++)
            #pragma unroll
            for (int ni = 0; ni < 4; ni++) {
                int r0 = wm * 32 + mi * 16 + gid;
                int cb = wn * 32 + ni * 8 + tig * 2;
                float bb0 = bm1[cc * 128 + cb], bb1 = bm1[cc * 128 + cb + 1];
                *(__half2*)(Gb + r0 * VSTR + cb) = __floats2half2_rn(
                    gelu_f(tacc[mi][ni][0] + bb0),
                    gelu_f(tacc[mi][ni][1] + bb1));
                *(__half2*)(Gb + (r0 + 8) * VSTR + cb) = __floats2half2_rn(
                    gelu_f(tacc[mi][ni][2] + bb0),
                    gelu_f(tacc[mi][ni][3] + bb1));
            }
        cp_wait<0>();
        __syncthreads();             // W2(cc) ready; Gb published
        mma_gemm128(Gb, Bw, uacc, wm, wn, lane);
        __syncthreads();

        if (cc < 3) {
            issueB128(g_W1T + (cc + 1) * 128 * DD, DD);
            cp_commit();
        }
    }

    // ---------------- z = y + u + bm2 -> direct global store --------------
    #pragma unroll
    for (int mi = 0; mi < 2; mi++)
        #pragma unroll
        for (int ni = 0; ni < 4; ni++) {
            int r0 = wm * 32 + mi * 16 + gid;
            int cb = wn * 32 + ni * 8 + tig * 2;
            float bb0 = bm2[cb], bb1 = bm2[cb + 1];
            float2 z0, z1;
            z0.x = Yb[r0 * YSTR + cb]       + uacc[mi][ni][0] + bb0;
            z0.y = Yb[r0 * YSTR + cb + 1]   + uacc[mi][ni][1] + bb1;
            z1.x = Yb[(r0+8) * YSTR + cb]   + uacc[mi][ni][2] + bb0;
            z1.y = Yb[(r0+8) * YSTR + cb+1] + uacc[mi][ni][3] + bb1;
            *(float2*)(out + (tile0 + r0) * DD + cb)     = z0;
            *(float2*)(out + (tile0 + r0 + 8) * DD + cb) = z1;
        }
}

// ------------------------------ launcher ----------------------------------
extern "C" void kernel_launch(void* const* d_in, const int* in_sizes, int n_in,
                              void* d_out, int out_size)
{
    const float* x   = (const float*)d_in[0];
    const float* g1  = (const float*)d_in[1];
    const float* b1  = (const float*)d_in[2];
    // d_in[3]=Wq, d_in[4]=bq, d_in[7]=rpb : dead
    const float* Wkv = (const float*)d_in[5];
    const float* bkv = (const float*)d_in[6];
    const float* Wp  = (const float*)d_in[8];
    const float* bp  = (const float*)d_in[9];
    const float* g2  = (const float*)d_in[10];
    const float* b2  = (const float*)d_in[11];
    const float* W1  = (const float*)d_in[12];
    const float* bm1 = (const float*)d_in[13];
    const float* W2  = (const float*)d_in[14];
    const float* bm2 = (const float*)d_in[15];
    float* out = (float*)d_out;

    cudaFuncSetAttribute(fused_mma,
                         cudaFuncAttributeMaxDynamicSharedMemorySize,
                         SMEM_BYTES);

    prep_kernel<<<192, 256>>>(Wkv, Wp, W1, W2);

    const int tokens = in_sizes[0] / CC;   // 65536
    const int grid   = tokens / MT;        // 1024
    fused_mma<<<grid, NTHR, SMEM_BYTES>>>(
        x, g1, b1, bkv, bp, g2, b2, bm1, bm2, out);
}

// round 8
// speedup vs baseline: 1.0129x; 1.0129x over previous
#include <cuda_runtime.h>
#include <cuda_fp16.h>
#include <math.h>
#include <stdint.h>

// ===========================================================================
// Live math (softmax over size-1 axis == 1 kills q/Wq/bq/rpb/k-half of Wkv):
//   h = LN(x;g1,b1); v = h@Wv+bv; y = v@Wp+bp;
//   z = y + gelu(LN(y;g2,b2)@W1+bm1)@W2 + bm2
// mma.sync m16n8k16 fp16 (fp32 accum), ldmatrix, single-shot K=128 B tiles
// with cross-phase cp.async prefetch.  64 tokens/CTA, 8 warps, 2 CTAs/SM.
// R8 = R6 structure (per-call B addressing) + 1-MUFU gelu only.
// ===========================================================================

#define CC    384
#define DD    128
#define HIDN  512
#define MT    64
#define NTHR  256
#define EPSV  1e-5f

#define BSTR  72     // K=64 chunk stride (halves); row step 144B -> ldsm-clean
#define WSTR  136    // K=128 tile stride (halves); row step 272B -> ldsm-clean
#define VSTR  136
#define YSTR  132

// smem byte offsets
#define OFF_BB   0                    // B region: max(2x128x72, 128x136)x2 = 36864
#define OFF_VB   36864                // v / lny : 64 x 136 fp16 = 17408
#define OFF_GB   54272                // gelu    : 64 x 136 fp16 (A-chunk aliases)
#define OFF_YB   71680                // y       : 64 x 132 fp32 = 33792
#define OFF_MEAN 105472
#define OFF_RSTD 105728
#define SMEM_BYTES 105984

// Pre-transposed fp16 weights, [n][k] row-major (mma row.col B operand)
__device__ __half g_WvT[DD * CC];
__device__ __half g_WpT[DD * DD];
__device__ __half g_W1T[HIDN * DD];
__device__ __half g_W2T[DD * HIDN];

__device__ __forceinline__ uint32_t smem_u32(const void* p) {
    uint32_t a;
    asm("{ .reg .u64 t; cvta.to.shared.u64 t, %1; cvt.u32.u64 %0, t; }"
        : "=r"(a) : "l"(p));
    return a;
}
__device__ __forceinline__ void cp16(uint32_t dst, const void* src) {
    asm volatile("cp.async.cg.shared.global [%0], [%1], 16;"
                 :: "r"(dst), "l"(src));
}
__device__ __forceinline__ void cp_commit() {
    asm volatile("cp.async.commit_group;" ::: "memory");
}
template<int N> __device__ __forceinline__ void cp_wait() {
    asm volatile("cp.async.wait_group %0;" :: "n"(N) : "memory");
}
__device__ __forceinline__ void ldsm4(uint32_t r[4], uint32_t addr) {
    asm volatile("ldmatrix.sync.aligned.m8n8.x4.shared.b16 {%0,%1,%2,%3}, [%4];"
                 : "=r"(r[0]), "=r"(r[1]), "=r"(r[2]), "=r"(r[3]) : "r"(addr));
}
__device__ __forceinline__ void mma16(float c[4],
    uint32_t a0, uint32_t a1, uint32_t a2, uint32_t a3,
    uint32_t b0, uint32_t b1) {
    asm volatile(
        "mma.sync.aligned.m16n8k16.row.col.f32.f16.f16.f32 "
        "{%0,%1,%2,%3}, {%4,%5,%6,%7}, {%8,%9}, {%0,%1,%2,%3};"
        : "+f"(c[0]), "+f"(c[1]), "+f"(c[2]), "+f"(c[3])
        : "r"(a0), "r"(a1), "r"(a2), "r"(a3), "r"(b0), "r"(b1));
}

// Gelu with exact erf via A&S 7.1.28: erf(x) = 1 - (1+a1 x+...+a6 x^6)^-16.
// Abs err ~2e-5 (<< fp16 operand rounding). ONE MUFU (rcp), rest FMA/mul.
__device__ __forceinline__ float gelu_f(float v) {
    float x = fabsf(v) * 0.70710678118654752f;
    float d = fmaf(x, 0.0000430638f, 0.0002765672f);
    d = fmaf(d, x, 0.0001520143f);
    d = fmaf(d, x, 0.0092705272f);
    d = fmaf(d, x, 0.0422820123f);
    d = fmaf(d, x, 0.0705230784f);
    d = fmaf(d, x, 1.0f);
    float r = __frcp_rn(d);          // MUFU.RCP
    float r2  = r * r;
    float r4  = r2 * r2;
    float r8  = r4 * r4;
    float r16 = r8 * r8;
    float er  = 1.f - r16;           // erf(|x|)
    return 0.5f * v * (1.f + copysignf(er, v));
}

// ----- MMA bodies ---------------------------------------------------------
#define MMA_KSTEP(acc, aA0, aA1, aB0, aB1, koff) { \
    uint32_t a0[4], a1[4], b0[4], b1[4]; \
    ldsm4(a0, (aA0) + (koff)); ldsm4(a1, (aA1) + (koff)); \
    ldsm4(b0, (aB0) + (koff)); ldsm4(b1, (aB1) + (koff)); \
    mma16(acc[0][0], a0[0],a0[1],a0[2],a0[3], b0[0], b0[2]); \
    mma16(acc[0][1], a0[0],a0[1],a0[2],a0[3], b0[1], b0[3]); \
    mma16(acc[0][2], a0[0],a0[1],a0[2],a0[3], b1[0], b1[2]); \
    mma16(acc[0][3], a0[0],a0[1],a0[2],a0[3], b1[1], b1[3]); \
    mma16(acc[1][0], a1[0],a1[1],a1[2],a1[3], b0[0], b0[2]); \
    mma16(acc[1][1], a1[0],a1[1],a1[2],a1[3], b0[1], b0[3]); \
    mma16(acc[1][2], a1[0],a1[1],a1[2],a1[3], b1[0], b1[2]); \
    mma16(acc[1][3], a1[0],a1[1],a1[2],a1[3], b1[1], b1[3]); \
}

// K=64 chunk (stage 2): A stride lda, B stride BSTR
__device__ __forceinline__ void mma_chunk64(
    const __half* As, int lda, const __half* Bs,
    float acc[2][4][4], int wm, int wn, int lane)
{
    const int lrow = lane & 15;
    const int lcol = (lane >> 4) << 3;
    uint32_t aA0 = smem_u32(As + (wm * 32 +      lrow) * lda + lcol);
    uint32_t aA1 = smem_u32(As + (wm * 32 + 16 + lrow) * lda + lcol);
    uint32_t aB0 = smem_u32(Bs + (wn * 32 +      lrow) * BSTR + lcol);
    uint32_t aB1 = smem_u32(Bs + (wn * 32 + 16 + lrow) * BSTR + lcol);
    #pragma unroll
    for (int k0 = 0; k0 < 64; k0 += 16)
        MMA_KSTEP(acc, aA0, aA1, aB0, aB1, k0 * 2);
}

// K=128 GEMM: A stride VSTR, B stride WSTR (single tile)
__device__ __forceinline__ void mma_gemm128(
    const __half* As, const __half* Bs,
    float acc[2][4][4], int wm, int wn, int lane)
{
    const int lrow = lane & 15;
    const int lcol = (lane >> 4) << 3;
    uint32_t aA0 = smem_u32(As + (wm * 32 +      lrow) * VSTR + lcol);
    uint32_t aA1 = smem_u32(As + (wm * 32 + 16 + lrow) * VSTR + lcol);
    uint32_t aB0 = smem_u32(Bs + (wn * 32 +      lrow) * WSTR + lcol);
    uint32_t aB1 = smem_u32(Bs + (wn * 32 + 16 + lrow) * WSTR + lcol);
    #pragma unroll
    for (int k0 = 0; k0 < 128; k0 += 16)
        MMA_KSTEP(acc, aA0, aA1, aB0, aB1, k0 * 2);
}

// ----- async B loaders (per-call addressing, as in R6) --------------------
__device__ __forceinline__ void issueB64(__half* Bdst, const __half* __restrict__ Wg,
                                         int ldw, int kc, int tid)
{
    #pragma unroll
    for (int i = 0; i < 4; i++) {
        int idx = tid + NTHR * i;
        int row = idx >> 3;
        int g8  = (idx & 7) << 3;
        cp16(smem_u32(Bdst + row * BSTR + g8), Wg + row * ldw + kc + g8);
    }
}
__device__ __forceinline__ void issueB128(__half* Bdst, const __half* __restrict__ Wg,
                                          int ldw, int tid)
{
    #pragma unroll
    for (int i = 0; i < 8; i++) {
        int idx = tid + NTHR * i;
        int row = idx >> 4;
        int g8  = (idx & 15) << 3;
        cp16(smem_u32(Bdst + row * WSTR + g8), Wg + row * ldw + g8);
    }
}

#define ZERO_ACC(A) { _Pragma("unroll") for (int _m=0;_m<2;_m++) \
    _Pragma("unroll") for (int _n=0;_n<4;_n++) \
    _Pragma("unroll") for (int _q=0;_q<4;_q++) (A)[_m][_n][_q] = 0.f; }

// --------------------------- weight prep kernel ---------------------------
__global__ void prep_kernel(const float* __restrict__ Wkv,
                            const float* __restrict__ Wp,
                            const float* __restrict__ W1,
                            const float* __restrict__ W2) {
    int tid = blockIdx.x * blockDim.x + threadIdx.x;
    int str = gridDim.x * blockDim.x;
    for (int s = tid; s < CC * DD; s += str) {
        int k = s / DD, n = s % DD;
        g_WvT[n * CC + k] = __float2half_rn(Wkv[k * 256 + 128 + n]);
    }
    for (int s = tid; s < DD * DD; s += str) {
        int k = s / DD, n = s % DD;
        g_WpT[n * DD + k] = __float2half_rn(Wp[k * DD + n]);
    }
    for (int s = tid; s < DD * HIDN; s += str) {
        int k = s / HIDN, n = s % HIDN;
        g_W1T[n * DD + k] = __float2half_rn(W1[k * HIDN + n]);
    }
    for (int s = tid; s < HIDN * DD; s += str) {
        int k = s / DD, n = s % DD;
        g_W2T[n * HIDN + k] = __float2half_rn(W2[k * DD + n]);
    }
}

// ------------------------------ main kernel -------------------------------
extern __shared__ char smem_raw[];

__global__ void __launch_bounds__(NTHR, 2) fused_mma(
    const float* __restrict__ x,
    const float* __restrict__ g1, const float* __restrict__ b1,
    const float* __restrict__ bkv, const float* __restrict__ bp,
    const float* __restrict__ g2, const float* __restrict__ b2,
    const float* __restrict__ bm1, const float* __restrict__ bm2,
    float* __restrict__ out)
{
    __half* Bb0 = (__half*)(smem_raw + OFF_BB);
    __half* Bb1 = Bb0 + 128 * BSTR;
    __half* Bw  = Bb0;                           // K=128 tile (same region)
    __half* Vb  = (__half*)(smem_raw + OFF_VB);
    __half* Gb  = (__half*)(smem_raw + OFF_GB);
    __half* Ab  = (__half*)(smem_raw + OFF_GB);  // alias: stage-2 only
    float*  Yb  = (float*)(smem_raw + OFF_YB);
    float* smean = (float*)(smem_raw + OFF_MEAN);
    float* srstd = (float*)(smem_raw + OFF_RSTD);

    const int tid  = threadIdx.x;
    const int lane = tid & 31;
    const int warp = tid >> 5;
    const int wm   = warp >> 2;      // 0..1 (M tile)
    const int wn   = warp & 3;       // 0..3 (N tile)
    const int gid  = lane >> 2;      // 0..7
    const int tig  = lane & 3;       // 0..3
    const long tile0 = (long)blockIdx.x * MT;

    // Prefetch first Wv B-chunk: hides under LN stats.
    issueB64(Bb0, g_WvT, CC, 0, tid); cp_commit();

    // ---------------- LN(x) stats (8 rows per warp) ----------------
    #pragma unroll 1
    for (int i = 0; i < 8; i++) {
        int row = warp * 8 + i;
        const float* xr = x + (tile0 + row) * CC;
        float s = 0.f, ss = 0.f;
        #pragma unroll
        for (int u = 0; u < 12; u++) {
            float t = xr[lane + 32 * u];
            s += t; ss += t * t;
        }
        #pragma unroll
        for (int o = 16; o > 0; o >>= 1) {
            s  += __shfl_xor_sync(0xffffffffu, s,  o);
            ss += __shfl_xor_sync(0xffffffffu, ss, o);
        }
        if (lane == 0) {
            float m = s * (1.f / 384.f);
            float v = ss * (1.f / 384.f) - m * m;
            smean[row] = m;
            srstd[row] = rsqrtf(v + EPSV);
        }
    }
    __syncthreads();

    // ---------------- v = LN(x) @ WvT  (K=384, 6 x K=64 chunks) -----------
    float vacc[2][4][4];
    ZERO_ACC(vacc);
    #pragma unroll 1
    for (int c = 0; c < 6; c++) {
        __half* Bcur = (c & 1) ? Bb1 : Bb0;
        if (c < 5) {
            issueB64((c & 1) ? Bb0 : Bb1, g_WvT, CC, (c + 1) * 64, tid);
            cp_commit();
        }
        // fill A chunk: normalize x[:, kc..kc+63] -> fp16 (float4 loads)
        int kc = c * 64;
        #pragma unroll
        for (int i = 0; i < 4; i++) {
            int idx = tid + NTHR * i;            // 64 rows x 16 quads
            int row = idx >> 4, q = (idx & 15) * 4;
            int k = kc + q;
            float4 xx = *(const float4*)(x + (tile0 + row) * CC + k);
            float4 gg = *(const float4*)(g1 + k);
            float4 bb = *(const float4*)(b1 + k);
            float m = smean[row], rs = srstd[row];
            __half2 h0 = __floats2half2_rn(fmaf((xx.x - m) * rs, gg.x, bb.x),
                                           fmaf((xx.y - m) * rs, gg.y, bb.y));
            __half2 h1 = __floats2half2_rn(fmaf((xx.z - m) * rs, gg.z, bb.z),
                                           fmaf((xx.w - m) * rs, gg.w, bb.w));
            uint2 pk = make_uint2(*(uint32_t*)&h0, *(uint32_t*)&h1);
            *(uint2*)(Ab + row * BSTR + q) = pk;
        }
        if (c < 5) cp_wait<1>(); else cp_wait<0>();
        __syncthreads();
        mma_chunk64(Ab, BSTR, Bcur, vacc, wm, wn, lane);
        __syncthreads();
    }

    // Prefetch full Wp tile: hides under v epilogue.
    issueB128(Bw, g_WpT, DD, tid); cp_commit();

    // v epilogue -> Vb (fp16)
    #pragma unroll
    for (int mi = 0; mi < 2; mi++)
        #pragma unroll
        for (int ni = 0; ni < 4; ni++) {
            int r0 = wm * 32 + mi * 16 + gid;
            int cb = wn * 32 + ni * 8 + tig * 2;
            float b0 = bkv[128 + cb], b1v = bkv[129 + cb];
            *(__half2*)(Vb + r0 * VSTR + cb) =
                __floats2half2_rn(vacc[mi][ni][0] + b0, vacc[mi][ni][1] + b1v);
            *(__half2*)(Vb + (r0 + 8) * VSTR + cb) =
                __floats2half2_rn(vacc[mi][ni][2] + b0, vacc[mi][ni][3] + b1v);
        }

    // ---------------- y = v @ WpT (K=128, single tile) ----------------
    float yacc[2][4][4];
    ZERO_ACC(yacc);
    cp_wait<0>();
    __syncthreads();                 // Wp ready; Vb published
    mma_gemm128(Vb, Bw, yacc, wm, wn, lane);
    __syncthreads();

    // Prefetch W1 tile0: hides under y epilogue + LN(y).
    issueB128(Bw, g_W1T, DD, tid); cp_commit();

    // y epilogue -> Yb (fp32)
    #pragma unroll
    for (int mi = 0; mi < 2; mi++)
        #pragma unroll
        for (int ni = 0; ni < 4; ni++) {
            int r0 = wm * 32 + mi * 16 + gid;
            int cb = wn * 32 + ni * 8 + tig * 2;
            Yb[r0 * YSTR + cb]         = yacc[mi][ni][0] + bp[cb];
            Yb[r0 * YSTR + cb + 1]     = yacc[mi][ni][1] + bp[cb + 1];
            Yb[(r0 + 8) * YSTR + cb]   = yacc[mi][ni][2] + bp[cb];
            Yb[(r0 + 8) * YSTR + cb+1] = yacc[mi][ni][3] + bp[cb + 1];
        }
    __syncthreads();                 // publish Yb

    // lny = LN(y) -> Vb (fp16)
    #pragma unroll 1
    for (int i = 0; i < 8; i++) {
        int row = warp * 8 + i;
        float vals[4];
        float s = 0.f, ss = 0.f;
        #pragma unroll
        for (int u = 0; u < 4; u++) {
            float t = Yb[row * YSTR + lane + 32 * u];
            vals[u] = t; s += t; ss += t * t;
        }
        #pragma unroll
        for (int o = 16; o > 0; o >>= 1) {
            s  += __shfl_xor_sync(0xffffffffu, s,  o);
            ss += __shfl_xor_sync(0xffffffffu, ss, o);
        }
        float m  = s * (1.f / 128.f);
        float vv = ss * (1.f / 128.f) - m * m;
        float rs = rsqrtf(vv + EPSV);
        #pragma unroll
        for (int u = 0; u < 4; u++) {
            int k = lane + 32 * u;
            Vb[row * VSTR + k] =
                __float2half_rn((vals[u] - m) * rs * g2[k] + b2[k]);
        }
    }

    // ---------------- MLP: 4 hidden tiles of 128 ----------------
    float uacc[2][4][4];
    ZERO_ACC(uacc);
    #pragma unroll 1
    for (int cc = 0; cc < 4; cc++) {
        cp_wait<0>();
        __syncthreads();             // W1(cc) ready; lny/Gb published
        float tacc[2][4][4];
        ZERO_ACC(tacc);
        mma_gemm128(Vb, Bw, tacc, wm, wn, lane);
        __syncthreads();

        issueB128(Bw, g_W2T + cc * 128, HIDN, tid); cp_commit();

        // gelu epilogue -> Gb (fp16)
        #pragma unroll
        for (int mi = 0; mi < 2; mi++)
            #pragma unroll
            for (int ni = 0; ni < 4; ni++) {
                int r0 = wm * 32 + mi * 16 + gid;
                int cb = wn * 32 + ni * 8 + tig * 2;
                float bb0 = bm1[cc * 128 + cb], bb1 = bm1[cc * 128 + cb + 1];
                *(__half2*)(Gb + r0 * VSTR + cb) = __floats2half2_rn(
                    gelu_f(tacc[mi][ni][0] + bb0),
                    gelu_f(tacc[mi][ni][1] + bb1));
                *(__half2*)(Gb + (r0 + 8) * VSTR + cb) = __floats2half2_rn(
                    gelu_f(tacc[mi][ni][2] + bb0),
                    gelu_f(tacc[mi][ni][3] + bb1));
            }
        cp_wait<0>();
        __syncthreads();             // W2(cc) ready; Gb published
        mma_gemm128(Gb, Bw, uacc, wm, wn, lane);
        __syncthreads();

        if (cc < 3) {
            issueB128(Bw, g_W1T + (cc + 1) * 128 * DD, DD, tid);
            cp_commit();
        }
    }

    // ---------------- z = y + u + bm2 -> direct global store --------------
    #pragma unroll
    for (int mi = 0; mi < 2; mi++)
        #pragma unroll
        for (int ni = 0; ni < 4; ni++) {
            int r0 = wm * 32 + mi * 16 + gid;
            int cb = wn * 32 + ni * 8 + tig * 2;
            float bb0 = bm2[cb], bb1 = bm2[cb + 1];
            float2 z0, z1;
            z0.x = Yb[r0 * YSTR + cb]       + uacc[mi][ni][0] + bb0;
            z0.y = Yb[r0 * YSTR + cb + 1]   + uacc[mi][ni][1] + bb1;
            z1.x = Yb[(r0+8) * YSTR + cb]   + uacc[mi][ni][2] + bb0;
            z1.y = Yb[(r0+8) * YSTR + cb+1] + uacc[mi][ni][3] + bb1;
            *(float2*)(out + (tile0 + r0) * DD + cb)     = z0;
            *(float2*)(out + (tile0 + r0 + 8) * DD + cb) = z1;
        }
}

// ------------------------------ launcher ----------------------------------
extern "C" void kernel_launch(void* const* d_in, const int* in_sizes, int n_in,
                              void* d_out, int out_size)
{
    const float* x   = (const float*)d_in[0];
    const float* g1  = (const float*)d_in[1];
    const float* b1  = (const float*)d_in[2];
    // d_in[3]=Wq, d_in[4]=bq, d_in[7]=rpb : dead
    const float* Wkv = (const float*)d_in[5];
    const float* bkv = (const float*)d_in[6];
    const float* Wp  = (const float*)d_in[8];
    const float* bp  = (const float*)d_in[9];
    const float* g2  = (const float*)d_in[10];
    const float* b2  = (const float*)d_in[11];
    const float* W1  = (const float*)d_in[12];
    const float* bm1 = (const float*)d_in[13];
    const float* W2  = (const float*)d_in[14];
    const float* bm2 = (const float*)d_in[15];
    float* out = (float*)d_out;

    cudaFuncSetAttribute(fused_mma,
                         cudaFuncAttributeMaxDynamicSharedMemorySize,
                         SMEM_BYTES);

    prep_kernel<<<192, 256>>>(Wkv, Wp, W1, W2);

    const int tokens = in_sizes[0] / CC;   // 65536
    const int grid   = tokens / MT;        // 1024
    fused_mma<<<grid, NTHR, SMEM_BYTES>>>(
        x, g1, b1, bkv, bp, g2, b2, bm1, bm2, out);
}

// round 9
// speedup vs baseline: 1.1164x; 1.1022x over previous
#include <cuda_runtime.h>
#include <cuda_fp16.h>
#include <math.h>
#include <stdint.h>

// ===========================================================================
// Live math (softmax over size-1 axis == 1 kills q/Wq/bq/rpb/k-half of Wkv):
//   h = LN(x;g1,b1); v = h@Wv+bv; y = v@Wp+bp;
//   z = y + gelu(LN(y;g2,b2)@W1+bm1)@W2 + bm2
// mma.sync m16n8k16 fp16 (fp32 accum), ldmatrix, single-shot K=128 B tiles
// with cross-phase cp.async prefetch.  64 tokens/CTA, 8 warps, 2 CTAs/SM.
// R9 = R6 main kernel exactly (best measured) + coalesced tiled-transpose prep.
// ===========================================================================

#define CC    384
#define DD    128
#define HIDN  512
#define MT    64
#define NTHR  256
#define EPSV  1e-5f

#define BSTR  72     // K=64 chunk stride (halves); row step 144B -> ldsm-clean
#define WSTR  136    // K=128 tile stride (halves); row step 272B -> ldsm-clean
#define VSTR  136
#define YSTR  132

// smem byte offsets
#define OFF_BB   0                    // B region: max(2x128x72, 128x136)x2 = 36864
#define OFF_VB   36864                // v / lny : 64 x 136 fp16 = 17408
#define OFF_GB   54272                // gelu    : 64 x 136 fp16 (A-chunk aliases)
#define OFF_YB   71680                // y       : 64 x 132 fp32 = 33792
#define OFF_MEAN 105472
#define OFF_RSTD 105728
#define SMEM_BYTES 105984

// Pre-transposed fp16 weights, [n][k] row-major (mma row.col B operand)
__device__ __half g_WvT[DD * CC];
__device__ __half g_WpT[DD * DD];
__device__ __half g_W1T[HIDN * DD];
__device__ __half g_W2T[DD * HIDN];

__device__ __forceinline__ uint32_t smem_u32(const void* p) {
    uint32_t a;
    asm("{ .reg .u64 t; cvta.to.shared.u64 t, %1; cvt.u32.u64 %0, t; }"
        : "=r"(a) : "l"(p));
    return a;
}
__device__ __forceinline__ void cp16(uint32_t dst, const void* src) {
    asm volatile("cp.async.cg.shared.global [%0], [%1], 16;"
                 :: "r"(dst), "l"(src));
}
__device__ __forceinline__ void cp_commit() {
    asm volatile("cp.async.commit_group;" ::: "memory");
}
template<int N> __device__ __forceinline__ void cp_wait() {
    asm volatile("cp.async.wait_group %0;" :: "n"(N) : "memory");
}
__device__ __forceinline__ void ldsm4(uint32_t r[4], uint32_t addr) {
    asm volatile("ldmatrix.sync.aligned.m8n8.x4.shared.b16 {%0,%1,%2,%3}, [%4];"
                 : "=r"(r[0]), "=r"(r[1]), "=r"(r[2]), "=r"(r[3]) : "r"(addr));
}
__device__ __forceinline__ void mma16(float c[4],
    uint32_t a0, uint32_t a1, uint32_t a2, uint32_t a3,
    uint32_t b0, uint32_t b1) {
    asm volatile(
        "mma.sync.aligned.m16n8k16.row.col.f32.f16.f16.f32 "
        "{%0,%1,%2,%3}, {%4,%5,%6,%7}, {%8,%9}, {%0,%1,%2,%3};"
        : "+f"(c[0]), "+f"(c[1]), "+f"(c[2]), "+f"(c[3])
        : "r"(a0), "r"(a1), "r"(a2), "r"(a3), "r"(b0), "r"(b1));
}

// Fast exact-erf gelu (A&S 7.1.26, abs err ~1.5e-7; poly and expf overlap)
__device__ __forceinline__ float gelu_f(float v) {
    float x = fabsf(v) * 0.70710678118654752f;
    float w = __fdividef(1.f, fmaf(0.3275911f, x, 1.f));
    float p = fmaf(w, 1.061405429f, -1.453152027f);
    p = fmaf(p, w, 1.421413741f);
    p = fmaf(p, w, -0.284496736f);
    p = fmaf(p, w, 0.254829592f);
    p *= w;
    float e = __expf(-x * x);
    float er = fmaf(-p, e, 1.f);
    return 0.5f * v * (1.f + copysignf(er, v));
}

// ----- MMA bodies ---------------------------------------------------------
#define MMA_KSTEP(acc, aA0, aA1, aB0, aB1, koff) { \
    uint32_t a0[4], a1[4], b0[4], b1[4]; \
    ldsm4(a0, (aA0) + (koff)); ldsm4(a1, (aA1) + (koff)); \
    ldsm4(b0, (aB0) + (koff)); ldsm4(b1, (aB1) + (koff)); \
    mma16(acc[0][0], a0[0],a0[1],a0[2],a0[3], b0[0], b0[2]); \
    mma16(acc[0][1], a0[0],a0[1],a0[2],a0[3], b0[1], b0[3]); \
    mma16(acc[0][2], a0[0],a0[1],a0[2],a0[3], b1[0], b1[2]); \
    mma16(acc[0][3], a0[0],a0[1],a0[2],a0[3], b1[1], b1[3]); \
    mma16(acc[1][0], a1[0],a1[1],a1[2],a1[3], b0[0], b0[2]); \
    mma16(acc[1][1], a1[0],a1[1],a1[2],a1[3], b0[1], b0[3]); \
    mma16(acc[1][2], a1[0],a1[1],a1[2],a1[3], b1[0], b1[2]); \
    mma16(acc[1][3], a1[0],a1[1],a1[2],a1[3], b1[1], b1[3]); \
}

// K=64 chunk (stage 2): A stride lda, B stride BSTR
__device__ __forceinline__ void mma_chunk64(
    const __half* As, int lda, const __half* Bs,
    float acc[2][4][4], int wm, int wn, int lane)
{
    const int lrow = lane & 15;
    const int lcol = (lane >> 4) << 3;
    uint32_t aA0 = smem_u32(As + (wm * 32 +      lrow) * lda + lcol);
    uint32_t aA1 = smem_u32(As + (wm * 32 + 16 + lrow) * lda + lcol);
    uint32_t aB0 = smem_u32(Bs + (wn * 32 +      lrow) * BSTR + lcol);
    uint32_t aB1 = smem_u32(Bs + (wn * 32 + 16 + lrow) * BSTR + lcol);
    #pragma unroll
    for (int k0 = 0; k0 < 64; k0 += 16)
        MMA_KSTEP(acc, aA0, aA1, aB0, aB1, k0 * 2);
}

// K=128 GEMM: A stride VSTR, B stride WSTR (single tile)
__device__ __forceinline__ void mma_gemm128(
    const __half* As, const __half* Bs,
    float acc[2][4][4], int wm, int wn, int lane)
{
    const int lrow = lane & 15;
    const int lcol = (lane >> 4) << 3;
    uint32_t aA0 = smem_u32(As + (wm * 32 +      lrow) * VSTR + lcol);
    uint32_t aA1 = smem_u32(As + (wm * 32 + 16 + lrow) * VSTR + lcol);
    uint32_t aB0 = smem_u32(Bs + (wn * 32 +      lrow) * WSTR + lcol);
    uint32_t aB1 = smem_u32(Bs + (wn * 32 + 16 + lrow) * WSTR + lcol);
    #pragma unroll
    for (int k0 = 0; k0 < 128; k0 += 16)
        MMA_KSTEP(acc, aA0, aA1, aB0, aB1, k0 * 2);
}

// ----- async B loaders ----------------------------------------------------
__device__ __forceinline__ void issueB64(__half* Bdst, const __half* __restrict__ Wg,
                                         int ldw, int kc, int tid)
{
    #pragma unroll
    for (int i = 0; i < 4; i++) {
        int idx = tid + NTHR * i;
        int row = idx >> 3;
        int g8  = (idx & 7) << 3;
        cp16(smem_u32(Bdst + row * BSTR + g8), Wg + row * ldw + kc + g8);
    }
}
__device__ __forceinline__ void issueB128(__half* Bdst, const __half* __restrict__ Wg,
                                          int ldw, int tid)
{
    #pragma unroll
    for (int i = 0; i < 8; i++) {
        int idx = tid + NTHR * i;
        int row = idx >> 4;
        int g8  = (idx & 15) << 3;
        cp16(smem_u32(Bdst + row * WSTR + g8), Wg + row * ldw + g8);
    }
}

#define ZERO_ACC(A) { _Pragma("unroll") for (int _m=0;_m<2;_m++) \
    _Pragma("unroll") for (int _n=0;_n<4;_n++) \
    _Pragma("unroll") for (int _q=0;_q<4;_q++) (A)[_m][_n][_q] = 0.f; }

// ------------------- coalesced tiled-transpose prep ------------------------
// dst[n*K + k] = half(src[k*lds + coloff + n]); 32x32 smem tiles, both sides
// coalesced. grid = (K/32, N/32), block = (32, 8).
__global__ void prep_t(const float* __restrict__ src, __half* __restrict__ dst,
                       int K, int lds, int coloff)
{
    __shared__ float tile[32][33];
    int k0 = blockIdx.x * 32, n0 = blockIdx.y * 32;
    int tx = threadIdx.x, ty = threadIdx.y;
    #pragma unroll
    for (int j = 0; j < 4; j++)
        tile[ty + 8 * j][tx] = src[(k0 + ty + 8 * j) * lds + coloff + n0 + tx];
    __syncthreads();
    #pragma unroll
    for (int j = 0; j < 4; j++)
        dst[(n0 + ty + 8 * j) * K + k0 + tx] =
            __float2half_rn(tile[tx][ty + 8 * j]);
}

// ------------------------------ main kernel -------------------------------
extern __shared__ char smem_raw[];

__global__ void __launch_bounds__(NTHR, 2) fused_mma(
    const float* __restrict__ x,
    const float* __restrict__ g1, const float* __restrict__ b1,
    const float* __restrict__ bkv, const float* __restrict__ bp,
    const float* __restrict__ g2, const float* __restrict__ b2,
    const float* __restrict__ bm1, const float* __restrict__ bm2,
    float* __restrict__ out)
{
    __half* Bb0 = (__half*)(smem_raw + OFF_BB);
    __half* Bb1 = Bb0 + 128 * BSTR;
    __half* Bw  = Bb0;                           // K=128 tile (same region)
    __half* Vb  = (__half*)(smem_raw + OFF_VB);
    __half* Gb  = (__half*)(smem_raw + OFF_GB);
    __half* Ab  = (__half*)(smem_raw + OFF_GB);  // alias: stage-2 only
    float*  Yb  = (float*)(smem_raw + OFF_YB);
    float* smean = (float*)(smem_raw + OFF_MEAN);
    float* srstd = (float*)(smem_raw + OFF_RSTD);

    const int tid  = threadIdx.x;
    const int lane = tid & 31;
    const int warp = tid >> 5;
    const int wm   = warp >> 2;      // 0..1 (M tile)
    const int wn   = warp & 3;       // 0..3 (N tile)
    const int gid  = lane >> 2;      // 0..7
    const int tig  = lane & 3;       // 0..3
    const long tile0 = (long)blockIdx.x * MT;

    // Prefetch first Wv B-chunk: hides under LN stats.
    issueB64(Bb0, g_WvT, CC, 0, tid); cp_commit();

    // ---------------- LN(x) stats (8 rows per warp) ----------------
    #pragma unroll 1
    for (int i = 0; i < 8; i++) {
        int row = warp * 8 + i;
        const float* xr = x + (tile0 + row) * CC;
        float s = 0.f, ss = 0.f;
        #pragma unroll
        for (int u = 0; u < 12; u++) {
            float t = xr[lane + 32 * u];
            s += t; ss += t * t;
        }
        #pragma unroll
        for (int o = 16; o > 0; o >>= 1) {
            s  += __shfl_xor_sync(0xffffffffu, s,  o);
            ss += __shfl_xor_sync(0xffffffffu, ss, o);
        }
        if (lane == 0) {
            float m = s * (1.f / 384.f);
            float v = ss * (1.f / 384.f) - m * m;
            smean[row] = m;
            srstd[row] = rsqrtf(v + EPSV);
        }
    }
    __syncthreads();

    // ---------------- v = LN(x) @ WvT  (K=384, 6 x K=64 chunks) -----------
    float vacc[2][4][4];
    ZERO_ACC(vacc);
    #pragma unroll 1
    for (int c = 0; c < 6; c++) {
        __half* Bcur = (c & 1) ? Bb1 : Bb0;
        if (c < 5) {
            issueB64((c & 1) ? Bb0 : Bb1, g_WvT, CC, (c + 1) * 64, tid);
            cp_commit();
        }
        // fill A chunk: normalize x[:, kc..kc+63] -> fp16 (float4 loads)
        int kc = c * 64;
        #pragma unroll
        for (int i = 0; i < 4; i++) {
            int idx = tid + NTHR * i;            // 64 rows x 16 quads
            int row = idx >> 4, q = (idx & 15) * 4;
            int k = kc + q;
            float4 xx = *(const float4*)(x + (tile0 + row) * CC + k);
            float4 gg = *(const float4*)(g1 + k);
            float4 bb = *(const float4*)(b1 + k);
            float m = smean[row], rs = srstd[row];
            __half2 h0 = __floats2half2_rn(fmaf((xx.x - m) * rs, gg.x, bb.x),
                                           fmaf((xx.y - m) * rs, gg.y, bb.y));
            __half2 h1 = __floats2half2_rn(fmaf((xx.z - m) * rs, gg.z, bb.z),
                                           fmaf((xx.w - m) * rs, gg.w, bb.w));
            uint2 pk = make_uint2(*(uint32_t*)&h0, *(uint32_t*)&h1);
            *(uint2*)(Ab + row * BSTR + q) = pk;
        }
        if (c < 5) cp_wait<1>(); else cp_wait<0>();
        __syncthreads();
        mma_chunk64(Ab, BSTR, Bcur, vacc, wm, wn, lane);
        __syncthreads();
    }

    // Prefetch full Wp tile: hides under v epilogue.
    issueB128(Bw, g_WpT, DD, tid); cp_commit();

    // v epilogue -> Vb (fp16)
    #pragma unroll
    for (int mi = 0; mi < 2; mi++)
        #pragma unroll
        for (int ni = 0; ni < 4; ni++) {
            int r0 = wm * 32 + mi * 16 + gid;
            int cb = wn * 32 + ni * 8 + tig * 2;
            float b0 = bkv[128 + cb], b1v = bkv[129 + cb];
            *(__half2*)(Vb + r0 * VSTR + cb) =
                __floats2half2_rn(vacc[mi][ni][0] + b0, vacc[mi][ni][1] + b1v);
            *(__half2*)(Vb + (r0 + 8) * VSTR + cb) =
                __floats2half2_rn(vacc[mi][ni][2] + b0, vacc[mi][ni][3] + b1v);
        }

    // ---------------- y = v @ WpT (K=128, single tile) ----------------
    float yacc[2][4][4];
    ZERO_ACC(yacc);
    cp_wait<0>();
    __syncthreads();                 // Wp ready; Vb published
    mma_gemm128(Vb, Bw, yacc, wm, wn, lane);
    __syncthreads();

    // Prefetch W1 tile0: hides under y epilogue + LN(y).
    issueB128(Bw, g_W1T, DD, tid); cp_commit();

    // y epilogue -> Yb (fp32)
    #pragma unroll
    for (int mi = 0; mi < 2; mi++)
        #pragma unroll
        for (int ni = 0; ni < 4; ni++) {
            int r0 = wm * 32 + mi * 16 + gid;
            int cb = wn * 32 + ni * 8 + tig * 2;
            Yb[r0 * YSTR + cb]         = yacc[mi][ni][0] + bp[cb];
            Yb[r0 * YSTR + cb + 1]     = yacc[mi][ni][1] + bp[cb + 1];
            Yb[(r0 + 8) * YSTR + cb]   = yacc[mi][ni][2] + bp[cb];
            Yb[(r0 + 8) * YSTR + cb+1] = yacc[mi][ni][3] + bp[cb + 1];
        }
    __syncthreads();                 // publish Yb

    // lny = LN(y) -> Vb (fp16)
    #pragma unroll 1
    for (int i = 0; i < 8; i++) {
        int row = warp * 8 + i;
        float vals[4];
        float s = 0.f, ss = 0.f;
        #pragma unroll
        for (int u = 0; u < 4; u++) {
            float t = Yb[row * YSTR + lane + 32 * u];
            vals[u] = t; s += t; ss += t * t;
        }
        #pragma unroll
        for (int o = 16; o > 0; o >>= 1) {
            s  += __shfl_xor_sync(0xffffffffu, s,  o);
            ss += __shfl_xor_sync(0xffffffffu, ss, o);
        }
        float m  = s * (1.f / 128.f);
        float vv = ss * (1.f / 128.f) - m * m;
        float rs = rsqrtf(vv + EPSV);
        #pragma unroll
        for (int u = 0; u < 4; u++) {
            int k = lane + 32 * u;
            Vb[row * VSTR + k] =
                __float2half_rn((vals[u] - m) * rs * g2[k] + b2[k]);
        }
    }

    // ---------------- MLP: 4 hidden tiles of 128 ----------------
    float uacc[2][4][4];
    ZERO_ACC(uacc);
    #pragma unroll 1
    for (int cc = 0; cc < 4; cc++) {
        cp_wait<0>();
        __syncthreads();             // W1(cc) ready; lny/Gb published
        float tacc[2][4][4];
        ZERO_ACC(tacc);
        mma_gemm128(Vb, Bw, tacc, wm, wn, lane);
        __syncthreads();

        issueB128(Bw, g_W2T + cc * 128, HIDN, tid); cp_commit();

        // gelu epilogue -> Gb (fp16)
        #pragma unroll
        for (int mi = 0; mi < 2; mi++)
            #pragma unroll
            for (int ni = 0; ni < 4; ni++) {
                int r0 = wm * 32 + mi * 16 + gid;
                int cb = wn * 32 + ni * 8 + tig * 2;
                float bb0 = bm1[cc * 128 + cb], bb1 = bm1[cc * 128 + cb + 1];
                *(__half2*)(Gb + r0 * VSTR + cb) = __floats2half2_rn(
                    gelu_f(tacc[mi][ni][0] + bb0),
                    gelu_f(tacc[mi][ni][1] + bb1));
                *(__half2*)(Gb + (r0 + 8) * VSTR + cb) = __floats2half2_rn(
                    gelu_f(tacc[mi][ni][2] + bb0),
                    gelu_f(tacc[mi][ni][3] + bb1));
            }
        cp_wait<0>();
        __syncthreads();             // W2(cc) ready; Gb published
        mma_gemm128(Gb, Bw, uacc, wm, wn, lane);
        __syncthreads();

        if (cc < 3) {
            issueB128(Bw, g_W1T + (cc + 1) * 128 * DD, DD, tid);
            cp_commit();
        }
    }

    // ---------------- z = y + u + bm2 -> direct global store --------------
    #pragma unroll
    for (int mi = 0; mi < 2; mi++)
        #pragma unroll
        for (int ni = 0; ni < 4; ni++) {
            int r0 = wm * 32 + mi * 16 + gid;
            int cb = wn * 32 + ni * 8 + tig * 2;
            float bb0 = bm2[cb], bb1 = bm2[cb + 1];
            float2 z0, z1;
            z0.x = Yb[r0 * YSTR + cb]       + uacc[mi][ni][0] + bb0;
            z0.y = Yb[r0 * YSTR + cb + 1]   + uacc[mi][ni][1] + bb1;
            z1.x = Yb[(r0+8) * YSTR + cb]   + uacc[mi][ni][2] + bb0;
            z1.y = Yb[(r0+8) * YSTR + cb+1] + uacc[mi][ni][3] + bb1;
            *(float2*)(out + (tile0 + r0) * DD + cb)     = z0;
            *(float2*)(out + (tile0 + r0 + 8) * DD + cb) = z1;
        }
}

// ------------------------------ launcher ----------------------------------
extern "C" void kernel_launch(void* const* d_in, const int* in_sizes, int n_in,
                              void* d_out, int out_size)
{
    const float* x   = (const float*)d_in[0];
    const float* g1  = (const float*)d_in[1];
    const float* b1  = (const float*)d_in[2];
    // d_in[3]=Wq, d_in[4]=bq, d_in[7]=rpb : dead
    const float* Wkv = (const float*)d_in[5];
    const float* bkv = (const float*)d_in[6];
    const float* Wp  = (const float*)d_in[8];
    const float* bp  = (const float*)d_in[9];
    const float* g2  = (const float*)d_in[10];
    const float* b2  = (const float*)d_in[11];
    const float* W1  = (const float*)d_in[12];
    const float* bm1 = (const float*)d_in[13];
    const float* W2  = (const float*)d_in[14];
    const float* bm2 = (const float*)d_in[15];
    float* out = (float*)d_out;

    cudaFuncSetAttribute(fused_mma,
                         cudaFuncAttributeMaxDynamicSharedMemorySize,
                         SMEM_BYTES);

    // Coalesced tiled transposes (fp32 -> fp16, [k][n] -> [n][k])
    {
        __half *WvT, *WpT, *W1T, *W2T;
        cudaGetSymbolAddress((void**)&WvT, g_WvT);
        cudaGetSymbolAddress((void**)&WpT, g_WpT);
        cudaGetSymbolAddress((void**)&W1T, g_W1T);
        cudaGetSymbolAddress((void**)&W2T, g_W2T);
        dim3 blk(32, 8);
        prep_t<<<dim3(CC / 32,   DD / 32),   blk>>>(Wkv, WvT, CC,   256, 128);
        prep_t<<<dim3(DD / 32,   DD / 32),   blk>>>(Wp,  WpT, DD,   DD,  0);
        prep_t<<<dim3(DD / 32,   HIDN / 32), blk>>>(W1,  W1T, DD,   HIDN, 0);
        prep_t<<<dim3(HIDN / 32, DD / 32),   blk>>>(W2,  W2T, HIDN, DD,  0);
    }

    const int tokens = in_sizes[0] / CC;   // 65536
    const int grid   = tokens / MT;        // 1024
    fused_mma<<<grid, NTHR, SMEM_BYTES>>>(
        x, g1, b1, bkv, bp, g2, b2, bm1, bm2, out);
}

// round 10
// speedup vs baseline: 1.1585x; 1.0377x over previous
#include <cuda_runtime.h>
#include <cuda_fp16.h>
#include <math.h>
#include <stdint.h>

// ===========================================================================
// Live math (softmax over size-1 axis == 1 kills q/Wq/bq/rpb/k-half of Wkv):
//   h = LN(x;g1,b1); v = h@Wv+bv; y = v@Wp+bp;
//   z = y + gelu(LN(y;g2,b2)@W1+bm1)@W2 + bm2
// mma.sync m16n8k16 fp16 (fp32 accum), ldmatrix, single-shot K=128 B tiles
// with cross-phase cp.async prefetch.  64 tokens/tile, 8 warps, 2 CTAs/SM.
// R10 = R6 tile body + PERSISTENT CTAs (atomic tile grab, kills wave
// quantization: 1024 tiles / ~300 slots = 3.4 waves was rounding to 4) +
// merged single-launch weight-prep kernel.
// ===========================================================================

#define CC    384
#define DD    128
#define HIDN  512
#define MT    64
#define NTHR  256
#define EPSV  1e-5f
#define PGRID 304    // persistent CTAs (2 per SM, 152 SMs on GB300)

#define BSTR  72     // K=64 chunk stride (halves); row step 144B -> ldsm-clean
#define WSTR  136    // K=128 tile stride (halves); row step 272B -> ldsm-clean
#define VSTR  136
#define YSTR  132

// smem byte offsets
#define OFF_BB   0                    // B region: max(2x128x72, 128x136)x2 = 36864
#define OFF_VB   36864                // v / lny : 64 x 136 fp16 = 17408
#define OFF_GB   54272                // gelu    : 64 x 136 fp16 (A-chunk aliases)
#define OFF_YB   71680                // y       : 64 x 132 fp32 = 33792
#define OFF_MEAN 105472
#define OFF_RSTD 105728
#define OFF_CTR  105984               // tile-index broadcast slot
#define SMEM_BYTES 106112

// Pre-transposed fp16 weights, [n][k] row-major (mma row.col B operand)
__device__ __half g_WvT[DD * CC];
__device__ __half g_WpT[DD * DD];
__device__ __half g_W1T[HIDN * DD];
__device__ __half g_W2T[DD * HIDN];
__device__ int    g_ctr;              // persistent tile counter

__device__ __forceinline__ uint32_t smem_u32(const void* p) {
    uint32_t a;
    asm("{ .reg .u64 t; cvta.to.shared.u64 t, %1; cvt.u32.u64 %0, t; }"
        : "=r"(a) : "l"(p));
    return a;
}
__device__ __forceinline__ void cp16(uint32_t dst, const void* src) {
    asm volatile("cp.async.cg.shared.global [%0], [%1], 16;"
                 :: "r"(dst), "l"(src));
}
__device__ __forceinline__ void cp_commit() {
    asm volatile("cp.async.commit_group;" ::: "memory");
}
template<int N> __device__ __forceinline__ void cp_wait() {
    asm volatile("cp.async.wait_group %0;" :: "n"(N) : "memory");
}
__device__ __forceinline__ void ldsm4(uint32_t r[4], uint32_t addr) {
    asm volatile("ldmatrix.sync.aligned.m8n8.x4.shared.b16 {%0,%1,%2,%3}, [%4];"
                 : "=r"(r[0]), "=r"(r[1]), "=r"(r[2]), "=r"(r[3]) : "r"(addr));
}
__device__ __forceinline__ void mma16(float c[4],
    uint32_t a0, uint32_t a1, uint32_t a2, uint32_t a3,
    uint32_t b0, uint32_t b1) {
    asm volatile(
        "mma.sync.aligned.m16n8k16.row.col.f32.f16.f16.f32 "
        "{%0,%1,%2,%3}, {%4,%5,%6,%7}, {%8,%9}, {%0,%1,%2,%3};"
        : "+f"(c[0]), "+f"(c[1]), "+f"(c[2]), "+f"(c[3])
        : "r"(a0), "r"(a1), "r"(a2), "r"(a3), "r"(b0), "r"(b1));
}

// Fast exact-erf gelu (A&S 7.1.26, abs err ~1.5e-7; poly and expf overlap)
__device__ __forceinline__ float gelu_f(float v) {
    float x = fabsf(v) * 0.70710678118654752f;
    float w = __fdividef(1.f, fmaf(0.3275911f, x, 1.f));
    float p = fmaf(w, 1.061405429f, -1.453152027f);
    p = fmaf(p, w, 1.421413741f);
    p = fmaf(p, w, -0.284496736f);
    p = fmaf(p, w, 0.254829592f);
    p *= w;
    float e = __expf(-x * x);
    float er = fmaf(-p, e, 1.f);
    return 0.5f * v * (1.f + copysignf(er, v));
}

// ----- MMA bodies ---------------------------------------------------------
#define MMA_KSTEP(acc, aA0, aA1, aB0, aB1, koff) { \
    uint32_t a0[4], a1[4], b0[4], b1[4]; \
    ldsm4(a0, (aA0) + (koff)); ldsm4(a1, (aA1) + (koff)); \
    ldsm4(b0, (aB0) + (koff)); ldsm4(b1, (aB1) + (koff)); \
    mma16(acc[0][0], a0[0],a0[1],a0[2],a0[3], b0[0], b0[2]); \
    mma16(acc[0][1], a0[0],a0[1],a0[2],a0[3], b0[1], b0[3]); \
    mma16(acc[0][2], a0[0],a0[1],a0[2],a0[3], b1[0], b1[2]); \
    mma16(acc[0][3], a0[0],a0[1],a0[2],a0[3], b1[1], b1[3]); \
    mma16(acc[1][0], a1[0],a1[1],a1[2],a1[3], b0[0], b0[2]); \
    mma16(acc[1][1], a1[0],a1[1],a1[2],a1[3], b0[1], b0[3]); \
    mma16(acc[1][2], a1[0],a1[1],a1[2],a1[3], b1[0], b1[2]); \
    mma16(acc[1][3], a1[0],a1[1],a1[2],a1[3], b1[1], b1[3]); \
}

// K=64 chunk (stage 2): A stride lda, B stride BSTR
__device__ __forceinline__ void mma_chunk64(
    const __half* As, int lda, const __half* Bs,
    float acc[2][4][4], int wm, int wn, int lane)
{
    const int lrow = lane & 15;
    const int lcol = (lane >> 4) << 3;
    uint32_t aA0 = smem_u32(As + (wm * 32 +      lrow) * lda + lcol);
    uint32_t aA1 = smem_u32(As + (wm * 32 + 16 + lrow) * lda + lcol);
    uint32_t aB0 = smem_u32(Bs + (wn * 32 +      lrow) * BSTR + lcol);
    uint32_t aB1 = smem_u32(Bs + (wn * 32 + 16 + lrow) * BSTR + lcol);
    #pragma unroll
    for (int k0 = 0; k0 < 64; k0 += 16)
        MMA_KSTEP(acc, aA0, aA1, aB0, aB1, k0 * 2);
}

// K=128 GEMM: A stride VSTR, B stride WSTR (single tile)
__device__ __forceinline__ void mma_gemm128(
    const __half* As, const __half* Bs,
    float acc[2][4][4], int wm, int wn, int lane)
{
    const int lrow = lane & 15;
    const int lcol = (lane >> 4) << 3;
    uint32_t aA0 = smem_u32(As + (wm * 32 +      lrow) * VSTR + lcol);
    uint32_t aA1 = smem_u32(As + (wm * 32 + 16 + lrow) * VSTR + lcol);
    uint32_t aB0 = smem_u32(Bs + (wn * 32 +      lrow) * WSTR + lcol);
    uint32_t aB1 = smem_u32(Bs + (wn * 32 + 16 + lrow) * WSTR + lcol);
    #pragma unroll
    for (int k0 = 0; k0 < 128; k0 += 16)
        MMA_KSTEP(acc, aA0, aA1, aB0, aB1, k0 * 2);
}

// ----- async B loaders ----------------------------------------------------
__device__ __forceinline__ void issueB64(__half* Bdst, const __half* __restrict__ Wg,
                                         int ldw, int kc, int tid)
{
    #pragma unroll
    for (int i = 0; i < 4; i++) {
        int idx = tid + NTHR * i;
        int row = idx >> 3;
        int g8  = (idx & 7) << 3;
        cp16(smem_u32(Bdst + row * BSTR + g8), Wg + row * ldw + kc + g8);
    }
}
__device__ __forceinline__ void issueB128(__half* Bdst, const __half* __restrict__ Wg,
                                          int ldw, int tid)
{
    #pragma unroll
    for (int i = 0; i < 8; i++) {
        int idx = tid + NTHR * i;
        int row = idx >> 4;
        int g8  = (idx & 15) << 3;
        cp16(smem_u32(Bdst + row * WSTR + g8), Wg + row * ldw + g8);
    }
}

#define ZERO_ACC(A) { _Pragma("unroll") for (int _m=0;_m<2;_m++) \
    _Pragma("unroll") for (int _n=0;_n<4;_n++) \
    _Pragma("unroll") for (int _q=0;_q<4;_q++) (A)[_m][_n][_q] = 0.f; }

// ---------------- merged weight-prep (one launch) + counter reset ---------
// 32x32 tiled transpose fp32->fp16, both sides coalesced.
// blocks: [0,48) Wv | [48,64) Wp | [64,128) W1 | [128,192) W2
__global__ void prep_all(const float* __restrict__ Wkv,
                         const float* __restrict__ Wp_,
                         const float* __restrict__ W1,
                         const float* __restrict__ W2)
{
    if (blockIdx.x == 0 && threadIdx.x == 0 && threadIdx.y == 0)
        g_ctr = 0;

    const float* src; __half* dst;
    int K, lds, coloff, kb, nb;
    int b = blockIdx.x;
    if (b < 48)       { src = Wkv; dst = g_WvT; K = CC;   lds = 256;  coloff = 128;
                        kb = b % 12;        nb = b / 12; }
    else if (b < 64)  { int i = b - 48;  src = Wp_; dst = g_WpT; K = DD;   lds = DD;
                        coloff = 0; kb = i % 4;  nb = i / 4; }
    else if (b < 128) { int i = b - 64;  src = W1;  dst = g_W1T; K = DD;   lds = HIDN;
                        coloff = 0; kb = i % 4;  nb = i / 4; }
    else              { int i = b - 128; src = W2;  dst = g_W2T; K = HIDN; lds = DD;
                        coloff = 0; kb = i % 16; nb = i / 16; }

    __shared__ float tile[32][33];
    int k0 = kb * 32, n0 = nb * 32;
    int tx = threadIdx.x, ty = threadIdx.y;
    #pragma unroll
    for (int j = 0; j < 4; j++)
        tile[ty + 8 * j][tx] = src[(k0 + ty + 8 * j) * lds + coloff + n0 + tx];
    __syncthreads();
    #pragma unroll
    for (int j = 0; j < 4; j++)
        dst[(n0 + ty + 8 * j) * K + k0 + tx] =
            __float2half_rn(tile[tx][ty + 8 * j]);
}

// ------------------------------ main kernel -------------------------------
extern __shared__ char smem_raw[];

__global__ void __launch_bounds__(NTHR, 2) fused_mma(
    const float* __restrict__ x,
    const float* __restrict__ g1, const float* __restrict__ b1,
    const float* __restrict__ bkv, const float* __restrict__ bp,
    const float* __restrict__ g2, const float* __restrict__ b2,
    const float* __restrict__ bm1, const float* __restrict__ bm2,
    float* __restrict__ out, int ntiles)
{
    __half* Bb0 = (__half*)(smem_raw + OFF_BB);
    __half* Bb1 = Bb0 + 128 * BSTR;
    __half* Bw  = Bb0;                           // K=128 tile (same region)
    __half* Vb  = (__half*)(smem_raw + OFF_VB);
    __half* Gb  = (__half*)(smem_raw + OFF_GB);
    __half* Ab  = (__half*)(smem_raw + OFF_GB);  // alias: stage-2 only
    float*  Yb  = (float*)(smem_raw + OFF_YB);
    float* smean = (float*)(smem_raw + OFF_MEAN);
    float* srstd = (float*)(smem_raw + OFF_RSTD);
    volatile int* stile = (volatile int*)(smem_raw + OFF_CTR);

    const int tid  = threadIdx.x;
    const int lane = tid & 31;
    const int warp = tid >> 5;
    const int wm   = warp >> 2;      // 0..1 (M tile)
    const int wn   = warp & 3;       // 0..3 (N tile)
    const int gid  = lane >> 2;      // 0..7
    const int tig  = lane & 3;       // 0..3

    for (;;) {
        if (tid == 0) *stile = atomicAdd(&g_ctr, 1);
        __syncthreads();             // broadcast tile idx; guard smem reuse
        int t = *stile;
        if (t >= ntiles) break;
        const long tile0 = (long)t * MT;

        // Prefetch first Wv B-chunk: hides under LN stats.
        issueB64(Bb0, g_WvT, CC, 0, tid); cp_commit();

        // ---------------- LN(x) stats (8 rows per warp) ----------------
        #pragma unroll 1
        for (int i = 0; i < 8; i++) {
            int row = warp * 8 + i;
            const float* xr = x + (tile0 + row) * CC;
            float s = 0.f, ss = 0.f;
            #pragma unroll
            for (int u = 0; u < 12; u++) {
                float tv = xr[lane + 32 * u];
                s += tv; ss += tv * tv;
            }
            #pragma unroll
            for (int o = 16; o > 0; o >>= 1) {
                s  += __shfl_xor_sync(0xffffffffu, s,  o);
                ss += __shfl_xor_sync(0xffffffffu, ss, o);
            }
            if (lane == 0) {
                float m = s * (1.f / 384.f);
                float v = ss * (1.f / 384.f) - m * m;
                smean[row] = m;
                srstd[row] = rsqrtf(v + EPSV);
            }
        }
        __syncthreads();

        // ------------- v = LN(x) @ WvT  (K=384, 6 x K=64 chunks) ----------
        float vacc[2][4][4];
        ZERO_ACC(vacc);
        #pragma unroll 1
        for (int c = 0; c < 6; c++) {
            __half* Bcur = (c & 1) ? Bb1 : Bb0;
            if (c < 5) {
                issueB64((c & 1) ? Bb0 : Bb1, g_WvT, CC, (c + 1) * 64, tid);
                cp_commit();
            }
            // fill A chunk: normalize x[:, kc..kc+63] -> fp16 (float4 loads)
            int kc = c * 64;
            #pragma unroll
            for (int i = 0; i < 4; i++) {
                int idx = tid + NTHR * i;            // 64 rows x 16 quads
                int row = idx >> 4, q = (idx & 15) * 4;
                int k = kc + q;
                float4 xx = *(const float4*)(x + (tile0 + row) * CC + k);
                float4 gg = *(const float4*)(g1 + k);
                float4 bb = *(const float4*)(b1 + k);
                float m = smean[row], rs = srstd[row];
                __half2 h0 = __floats2half2_rn(fmaf((xx.x - m) * rs, gg.x, bb.x),
                                               fmaf((xx.y - m) * rs, gg.y, bb.y));
                __half2 h1 = __floats2half2_rn(fmaf((xx.z - m) * rs, gg.z, bb.z),
                                               fmaf((xx.w - m) * rs, gg.w, bb.w));
                uint2 pk = make_uint2(*(uint32_t*)&h0, *(uint32_t*)&h1);
                *(uint2*)(Ab + row * BSTR + q) = pk;
            }
            if (c < 5) cp_wait<1>(); else cp_wait<0>();
            __syncthreads();
            mma_chunk64(Ab, BSTR, Bcur, vacc, wm, wn, lane);
            __syncthreads();
        }

        // Prefetch full Wp tile: hides under v epilogue.
        issueB128(Bw, g_WpT, DD, tid); cp_commit();

        // v epilogue -> Vb (fp16)
        #pragma unroll
        for (int mi = 0; mi < 2; mi++)
            #pragma unroll
            for (int ni = 0; ni < 4; ni++) {
                int r0 = wm * 32 + mi * 16 + gid;
                int cb = wn * 32 + ni * 8 + tig * 2;
                float b0 = bkv[128 + cb], b1v = bkv[129 + cb];
                *(__half2*)(Vb + r0 * VSTR + cb) =
                    __floats2half2_rn(vacc[mi][ni][0] + b0, vacc[mi][ni][1] + b1v);
                *(__half2*)(Vb + (r0 + 8) * VSTR + cb) =
                    __floats2half2_rn(vacc[mi][ni][2] + b0, vacc[mi][ni][3] + b1v);
            }

        // ------------- y = v @ WpT (K=128, single tile) -------------------
        float yacc[2][4][4];
        ZERO_ACC(yacc);
        cp_wait<0>();
        __syncthreads();                 // Wp ready; Vb published
        mma_gemm128(Vb, Bw, yacc, wm, wn, lane);
        __syncthreads();

        // Prefetch W1 tile0: hides under y epilogue + LN(y).
        issueB128(Bw, g_W1T, DD, tid); cp_commit();

        // y epilogue -> Yb (fp32)
        #pragma unroll
        for (int mi = 0; mi < 2; mi++)
            #pragma unroll
            for (int ni = 0; ni < 4; ni++) {
                int r0 = wm * 32 + mi * 16 + gid;
                int cb = wn * 32 + ni * 8 + tig * 2;
                Yb[r0 * YSTR + cb]         = yacc[mi][ni][0] + bp[cb];
                Yb[r0 * YSTR + cb + 1]     = yacc[mi][ni][1] + bp[cb + 1];
                Yb[(r0 + 8) * YSTR + cb]   = yacc[mi][ni][2] + bp[cb];
                Yb[(r0 + 8) * YSTR + cb+1] = yacc[mi][ni][3] + bp[cb + 1];
            }
        __syncthreads();                 // publish Yb

        // lny = LN(y) -> Vb (fp16)
        #pragma unroll 1
        for (int i = 0; i < 8; i++) {
            int row = warp * 8 + i;
            float vals[4];
            float s = 0.f, ss = 0.f;
            #pragma unroll
            for (int u = 0; u < 4; u++) {
                float tv = Yb[row * YSTR + lane + 32 * u];
                vals[u] = tv; s += tv; ss += tv * tv;
            }
            #pragma unroll
            for (int o = 16; o > 0; o >>= 1) {
                s  += __shfl_xor_sync(0xffffffffu, s,  o);
                ss += __shfl_xor_sync(0xffffffffu, ss, o);
            }
            float m  = s * (1.f / 128.f);
            float vv = ss * (1.f / 128.f) - m * m;
            float rs = rsqrtf(vv + EPSV);
            #pragma unroll
            for (int u = 0; u < 4; u++) {
                int k = lane + 32 * u;
                Vb[row * VSTR + k] =
                    __float2half_rn((vals[u] - m) * rs * g2[k] + b2[k]);
            }
        }

        // ---------------- MLP: 4 hidden tiles of 128 ----------------
        float uacc[2][4][4];
        ZERO_ACC(uacc);
        #pragma unroll 1
        for (int cc = 0; cc < 4; cc++) {
            cp_wait<0>();
            __syncthreads();             // W1(cc) ready; lny/Gb published
            float tacc[2][4][4];
            ZERO_ACC(tacc);
            mma_gemm128(Vb, Bw, tacc, wm, wn, lane);
            __syncthreads();

            issueB128(Bw, g_W2T + cc * 128, HIDN, tid); cp_commit();

            // gelu epilogue -> Gb (fp16)
            #pragma unroll
            for (int mi = 0; mi < 2; mi++)
                #pragma unroll
                for (int ni = 0; ni < 4; ni++) {
                    int r0 = wm * 32 + mi * 16 + gid;
                    int cb = wn * 32 + ni * 8 + tig * 2;
                    float bb0 = bm1[cc * 128 + cb], bb1 = bm1[cc * 128 + cb + 1];
                    *(__half2*)(Gb + r0 * VSTR + cb) = __floats2half2_rn(
                        gelu_f(tacc[mi][ni][0] + bb0),
                        gelu_f(tacc[mi][ni][1] + bb1));
                    *(__half2*)(Gb + (r0 + 8) * VSTR + cb) = __floats2half2_rn(
                        gelu_f(tacc[mi][ni][2] + bb0),
                        gelu_f(tacc[mi][ni][3] + bb1));
                }
            cp_wait<0>();
            __syncthreads();             // W2(cc) ready; Gb published
            mma_gemm128(Gb, Bw, uacc, wm, wn, lane);
            __syncthreads();

            if (cc < 3) {
                issueB128(Bw, g_W1T + (cc + 1) * 128 * DD, DD, tid);
                cp_commit();
            }
        }

        // ------------- z = y + u + bm2 -> direct global store -------------
        #pragma unroll
        for (int mi = 0; mi < 2; mi++)
            #pragma unroll
            for (int ni = 0; ni < 4; ni++) {
                int r0 = wm * 32 + mi * 16 + gid;
                int cb = wn * 32 + ni * 8 + tig * 2;
                float bb0 = bm2[cb], bb1 = bm2[cb + 1];
                float2 z0, z1;
                z0.x = Yb[r0 * YSTR + cb]       + uacc[mi][ni][0] + bb0;
                z0.y = Yb[r0 * YSTR + cb + 1]   + uacc[mi][ni][1] + bb1;
                z1.x = Yb[(r0+8) * YSTR + cb]   + uacc[mi][ni][2] + bb0;
                z1.y = Yb[(r0+8) * YSTR + cb+1] + uacc[mi][ni][3] + bb1;
                *(float2*)(out + (tile0 + r0) * DD + cb)     = z0;
                *(float2*)(out + (tile0 + r0 + 8) * DD + cb) = z1;
            }
    }
}

// ------------------------------ launcher ----------------------------------
extern "C" void kernel_launch(void* const* d_in, const int* in_sizes, int n_in,
                              void* d_out, int out_size)
{
    const float* x   = (const float*)d_in[0];
    const float* g1  = (const float*)d_in[1];
    const float* b1  = (const float*)d_in[2];
    // d_in[3]=Wq, d_in[4]=bq, d_in[7]=rpb : dead
    const float* Wkv = (const float*)d_in[5];
    const float* bkv = (const float*)d_in[6];
    const float* Wp  = (const float*)d_in[8];
    const float* bp  = (const float*)d_in[9];
    const float* g2  = (const float*)d_in[10];
    const float* b2  = (const float*)d_in[11];
    const float* W1  = (const float*)d_in[12];
    const float* bm1 = (const float*)d_in[13];
    const float* W2  = (const float*)d_in[14];
    const float* bm2 = (const float*)d_in[15];
    float* out = (float*)d_out;

    cudaFuncSetAttribute(fused_mma,
                         cudaFuncAttributeMaxDynamicSharedMemorySize,
                         SMEM_BYTES);

    prep_all<<<192, dim3(32, 8)>>>(Wkv, Wp, W1, W2);   // also resets g_ctr

    const int tokens = in_sizes[0] / CC;   // 65536
    const int ntiles = tokens / MT;        // 1024
    fused_mma<<<PGRID, NTHR, SMEM_BYTES>>>(
        x, g1, b1, bkv, bp, g2, b2, bm1, bm2, out, ntiles);
}

// round 11
// speedup vs baseline: 1.1616x; 1.0027x over previous
#include <cuda_runtime.h>
#include <cuda_fp16.h>
#include <math.h>
#include <stdint.h>

// ===========================================================================
// Live math (softmax over size-1 axis == 1 kills q/Wq/bq/rpb/k-half of Wkv):
//   h = LN(x;g1,b1); v = h@Wv+bv; y = v@Wp+bp;
//   z = y + gelu(LN(y;g2,b2)@W1+bm1)@W2 + bm2
// mma.sync m16n8k16 fp16 (fp32 accum), ldmatrix, persistent CTAs.
// R11: DOUBLE-BUFFERED K=128 weight tiles (BwA/BwB, loads issued 2 gemms
// ahead -> fully hidden); Yb smem eliminated (y -> registers -> global,
// LN(y) stats from fragments via shfl + 2KB psum buffer).
// ===========================================================================

#define CC    384
#define DD    128
#define HIDN  512
#define MT    64
#define NTHR  256
#define EPSV  1e-5f
#define PGRID 304    // persistent CTAs (2 per SM, 152 SMs)

#define BSTR  72     // K=64 chunk stride (halves)
#define WSTR  136    // K=128 tile stride (halves)
#define VSTR  136

// smem byte offsets
#define OFF_BB   0          // 2 x (128x136) fp16 = 69632 (stage-2 chunks alias)
#define OFF_VB   69632      // v / lny : 64 x 136 fp16 = 17408
#define OFF_GB   87040      // gelu    : 64 x 136 fp16 (A-chunk aliases)
#define OFF_PSUM 104448     // 256 fp32
#define OFF_PSQ  105472     // 256 fp32
#define OFF_MEAN 106496     // 64 fp32
#define OFF_RSTD 106752     // 64 fp32
#define OFF_CTR  107008
#define SMEM_BYTES 107136

// Pre-transposed fp16 weights, [n][k] row-major (mma row.col B operand)
__device__ __half g_WvT[DD * CC];
__device__ __half g_WpT[DD * DD];
__device__ __half g_W1T[HIDN * DD];
__device__ __half g_W2T[DD * HIDN];
__device__ int    g_ctr;

__device__ __forceinline__ uint32_t smem_u32(const void* p) {
    uint32_t a;
    asm("{ .reg .u64 t; cvta.to.shared.u64 t, %1; cvt.u32.u64 %0, t; }"
        : "=r"(a) : "l"(p));
    return a;
}
__device__ __forceinline__ void cp16(uint32_t dst, const void* src) {
    asm volatile("cp.async.cg.shared.global [%0], [%1], 16;"
                 :: "r"(dst), "l"(src));
}
__device__ __forceinline__ void cp_commit() {
    asm volatile("cp.async.commit_group;" ::: "memory");
}
template<int N> __device__ __forceinline__ void cp_wait() {
    asm volatile("cp.async.wait_group %0;" :: "n"(N) : "memory");
}
__device__ __forceinline__ void ldsm4(uint32_t r[4], uint32_t addr) {
    asm volatile("ldmatrix.sync.aligned.m8n8.x4.shared.b16 {%0,%1,%2,%3}, [%4];"
                 : "=r"(r[0]), "=r"(r[1]), "=r"(r[2]), "=r"(r[3]) : "r"(addr));
}
__device__ __forceinline__ void mma16(float c[4],
    uint32_t a0, uint32_t a1, uint32_t a2, uint32_t a3,
    uint32_t b0, uint32_t b1) {
    asm volatile(
        "mma.sync.aligned.m16n8k16.row.col.f32.f16.f16.f32 "
        "{%0,%1,%2,%3}, {%4,%5,%6,%7}, {%8,%9}, {%0,%1,%2,%3};"
        : "+f"(c[0]), "+f"(c[1]), "+f"(c[2]), "+f"(c[3])
        : "r"(a0), "r"(a1), "r"(a2), "r"(a3), "r"(b0), "r"(b1));
}

// Fast exact-erf gelu (A&S 7.1.26; poly and expf latency overlap)
__device__ __forceinline__ float gelu_f(float v) {
    float x = fabsf(v) * 0.70710678118654752f;
    float w = __fdividef(1.f, fmaf(0.3275911f, x, 1.f));
    float p = fmaf(w, 1.061405429f, -1.453152027f);
    p = fmaf(p, w, 1.421413741f);
    p = fmaf(p, w, -0.284496736f);
    p = fmaf(p, w, 0.254829592f);
    p *= w;
    float e = __expf(-x * x);
    float er = fmaf(-p, e, 1.f);
    return 0.5f * v * (1.f + copysignf(er, v));
}

// ----- MMA bodies ---------------------------------------------------------
#define MMA_KSTEP(acc, aA0, aA1, aB0, aB1, koff) { \
    uint32_t a0[4], a1[4], b0[4], b1[4]; \
    ldsm4(a0, (aA0) + (koff)); ldsm4(a1, (aA1) + (koff)); \
    ldsm4(b0, (aB0) + (koff)); ldsm4(b1, (aB1) + (koff)); \
    mma16(acc[0][0], a0[0],a0[1],a0[2],a0[3], b0[0], b0[2]); \
    mma16(acc[0][1], a0[0],a0[1],a0[2],a0[3], b0[1], b0[3]); \
    mma16(acc[0][2], a0[0],a0[1],a0[2],a0[3], b1[0], b1[2]); \
    mma16(acc[0][3], a0[0],a0[1],a0[2],a0[3], b1[1], b1[3]); \
    mma16(acc[1][0], a1[0],a1[1],a1[2],a1[3], b0[0], b0[2]); \
    mma16(acc[1][1], a1[0],a1[1],a1[2],a1[3], b0[1], b0[3]); \
    mma16(acc[1][2], a1[0],a1[1],a1[2],a1[3], b1[0], b1[2]); \
    mma16(acc[1][3], a1[0],a1[1],a1[2],a1[3], b1[1], b1[3]); \
}

__device__ __forceinline__ void mma_chunk64(
    const __half* As, int lda, const __half* Bs,
    float acc[2][4][4], int wm, int wn, int lane)
{
    const int lrow = lane & 15;
    const int lcol = (lane >> 4) << 3;
    uint32_t aA0 = smem_u32(As + (wm * 32 +      lrow) * lda + lcol);
    uint32_t aA1 = smem_u32(As + (wm * 32 + 16 + lrow) * lda + lcol);
    uint32_t aB0 = smem_u32(Bs + (wn * 32 +      lrow) * BSTR + lcol);
    uint32_t aB1 = smem_u32(Bs + (wn * 32 + 16 + lrow) * BSTR + lcol);
    #pragma unroll
    for (int k0 = 0; k0 < 64; k0 += 16)
        MMA_KSTEP(acc, aA0, aA1, aB0, aB1, k0 * 2);
}

__device__ __forceinline__ void mma_gemm128(
    const __half* As, const __half* Bs,
    float acc[2][4][4], int wm, int wn, int lane)
{
    const int lrow = lane & 15;
    const int lcol = (lane >> 4) << 3;
    uint32_t aA0 = smem_u32(As + (wm * 32 +      lrow) * VSTR + lcol);
    uint32_t aA1 = smem_u32(As + (wm * 32 + 16 + lrow) * VSTR + lcol);
    uint32_t aB0 = smem_u32(Bs + (wn * 32 +      lrow) * WSTR + lcol);
    uint32_t aB1 = smem_u32(Bs + (wn * 32 + 16 + lrow) * WSTR + lcol);
    #pragma unroll
    for (int k0 = 0; k0 < 128; k0 += 16)
        MMA_KSTEP(acc, aA0, aA1, aB0, aB1, k0 * 2);
}

// ----- async B loaders ----------------------------------------------------
__device__ __forceinline__ void issueB64(__half* Bdst, const __half* __restrict__ Wg,
                                         int ldw, int kc, int tid)
{
    #pragma unroll
    for (int i = 0; i < 4; i++) {
        int idx = tid + NTHR * i;
        int row = idx >> 3;
        int g8  = (idx & 7) << 3;
        cp16(smem_u32(Bdst + row * BSTR + g8), Wg + row * ldw + kc + g8);
    }
}
__device__ __forceinline__ void issueB128(__half* Bdst, const __half* __restrict__ Wg,
                                          int ldw, int tid)
{
    #pragma unroll
    for (int i = 0; i < 8; i++) {
        int idx = tid + NTHR * i;
        int row = idx >> 4;
        int g8  = (idx & 15) << 3;
        cp16(smem_u32(Bdst + row * WSTR + g8), Wg + row * ldw + g8);
    }
}

#define ZERO_ACC(A) { _Pragma("unroll") for (int _m=0;_m<2;_m++) \
    _Pragma("unroll") for (int _n=0;_n<4;_n++) \
    _Pragma("unroll") for (int _q=0;_q<4;_q++) (A)[_m][_n][_q] = 0.f; }

// ---------------- merged weight-prep (one launch) + counter reset ---------
__global__ void prep_all(const float* __restrict__ Wkv,
                         const float* __restrict__ Wp_,
                         const float* __restrict__ W1,
                         const float* __restrict__ W2)
{
    if (blockIdx.x == 0 && threadIdx.x == 0 && threadIdx.y == 0)
        g_ctr = 0;

    const float* src; __half* dst;
    int K, lds, coloff, kb, nb;
    int b = blockIdx.x;
    if (b < 48)       { src = Wkv; dst = g_WvT; K = CC;   lds = 256;  coloff = 128;
                        kb = b % 12;        nb = b / 12; }
    else if (b < 64)  { int i = b - 48;  src = Wp_; dst = g_WpT; K = DD;   lds = DD;
                        coloff = 0; kb = i % 4;  nb = i / 4; }
    else if (b < 128) { int i = b - 64;  src = W1;  dst = g_W1T; K = DD;   lds = HIDN;
                        coloff = 0; kb = i % 4;  nb = i / 4; }
    else              { int i = b - 128; src = W2;  dst = g_W2T; K = HIDN; lds = DD;
                        coloff = 0; kb = i % 16; nb = i / 16; }

    __shared__ float tile[32][33];
    int k0 = kb * 32, n0 = nb * 32;
    int tx = threadIdx.x, ty = threadIdx.y;
    #pragma unroll
    for (int j = 0; j < 4; j++)
        tile[ty + 8 * j][tx] = src[(k0 + ty + 8 * j) * lds + coloff + n0 + tx];
    __syncthreads();
    #pragma unroll
    for (int j = 0; j < 4; j++)
        dst[(n0 + ty + 8 * j) * K + k0 + tx] =
            __float2half_rn(tile[tx][ty + 8 * j]);
}

// ------------------------------ main kernel -------------------------------
extern __shared__ char smem_raw[];

__global__ void __launch_bounds__(NTHR, 2) fused_mma(
    const float* __restrict__ x,
    const float* __restrict__ g1, const float* __restrict__ b1,
    const float* __restrict__ bkv, const float* __restrict__ bp,
    const float* __restrict__ g2, const float* __restrict__ b2,
    const float* __restrict__ bm1, const float* __restrict__ bm2,
    float* __restrict__ out, int ntiles)
{
    __half* BwA = (__half*)(smem_raw + OFF_BB);
    __half* BwB = BwA + 128 * WSTR;              // second K=128 tile
    __half* Bb0 = BwA;                           // stage-2 K=64 chunk bufs
    __half* Bb1 = BwA + 128 * BSTR;
    __half* Vb  = (__half*)(smem_raw + OFF_VB);
    __half* Gb  = (__half*)(smem_raw + OFF_GB);
    __half* Ab  = (__half*)(smem_raw + OFF_GB);  // alias: stage-2 only
    float* psum  = (float*)(smem_raw + OFF_PSUM);
    float* psq   = (float*)(smem_raw + OFF_PSQ);
    float* smean = (float*)(smem_raw + OFF_MEAN);
    float* srstd = (float*)(smem_raw + OFF_RSTD);
    volatile int* stile = (volatile int*)(smem_raw + OFF_CTR);

    const int tid  = threadIdx.x;
    const int lane = tid & 31;
    const int warp = tid >> 5;
    const int wm   = warp >> 2;
    const int wn   = warp & 3;
    const int gid  = lane >> 2;
    const int tig  = lane & 3;

    for (;;) {
        if (tid == 0) *stile = atomicAdd(&g_ctr, 1);
        __syncthreads();
        int t = *stile;
        if (t >= ntiles) break;
        const long tile0 = (long)t * MT;

        issueB64(Bb0, g_WvT, CC, 0, tid); cp_commit();

        // ---------------- LN(x) stats ----------------
        #pragma unroll 1
        for (int i = 0; i < 8; i++) {
            int row = warp * 8 + i;
            const float* xr = x + (tile0 + row) * CC;
            float s = 0.f, ss = 0.f;
            #pragma unroll
            for (int u = 0; u < 12; u++) {
                float tv = xr[lane + 32 * u];
                s += tv; ss += tv * tv;
            }
            #pragma unroll
            for (int o = 16; o > 0; o >>= 1) {
                s  += __shfl_xor_sync(0xffffffffu, s,  o);
                ss += __shfl_xor_sync(0xffffffffu, ss, o);
            }
            if (lane == 0) {
                float m = s * (1.f / 384.f);
                float v = ss * (1.f / 384.f) - m * m;
                smean[row] = m;
                srstd[row] = rsqrtf(v + EPSV);
            }
        }
        __syncthreads();

        // ------------- v = LN(x) @ WvT  (K=384, 6 x K=64 chunks) ----------
        float vacc[2][4][4];
        ZERO_ACC(vacc);
        #pragma unroll 1
        for (int c = 0; c < 6; c++) {
            __half* Bcur = (c & 1) ? Bb1 : Bb0;
            if (c < 5) {
                issueB64((c & 1) ? Bb0 : Bb1, g_WvT, CC, (c + 1) * 64, tid);
                cp_commit();
            }
            int kc = c * 64;
            #pragma unroll
            for (int i = 0; i < 4; i++) {
                int idx = tid + NTHR * i;
                int row = idx >> 4, q = (idx & 15) * 4;
                int k = kc + q;
                float4 xx = *(const float4*)(x + (tile0 + row) * CC + k);
                float4 gg = *(const float4*)(g1 + k);
                float4 bb = *(const float4*)(b1 + k);
                float m = smean[row], rs = srstd[row];
                __half2 h0 = __floats2half2_rn(fmaf((xx.x - m) * rs, gg.x, bb.x),
                                               fmaf((xx.y - m) * rs, gg.y, bb.y));
                __half2 h1 = __floats2half2_rn(fmaf((xx.z - m) * rs, gg.z, bb.z),
                                               fmaf((xx.w - m) * rs, gg.w, bb.w));
                uint2 pk = make_uint2(*(uint32_t*)&h0, *(uint32_t*)&h1);
                *(uint2*)(Ab + row * BSTR + q) = pk;
            }
            if (c < 5) cp_wait<1>(); else cp_wait<0>();
            __syncthreads();
            mma_chunk64(Ab, BSTR, Bcur, vacc, wm, wn, lane);
            __syncthreads();
        }

        // Prefetch Wp -> BwA and W1(0) -> BwB (hidden under v epilogue)
        issueB128(BwA, g_WpT, DD, tid); cp_commit();
        issueB128(BwB, g_W1T, DD, tid); cp_commit();

        // v epilogue -> Vb (fp16)
        #pragma unroll
        for (int mi = 0; mi < 2; mi++)
            #pragma unroll
            for (int ni = 0; ni < 4; ni++) {
                int r0 = wm * 32 + mi * 16 + gid;
                int cb = wn * 32 + ni * 8 + tig * 2;
                float b0 = bkv[128 + cb], b1v = bkv[129 + cb];
                *(__half2*)(Vb + r0 * VSTR + cb) =
                    __floats2half2_rn(vacc[mi][ni][0] + b0, vacc[mi][ni][1] + b1v);
                *(__half2*)(Vb + (r0 + 8) * VSTR + cb) =
                    __floats2half2_rn(vacc[mi][ni][2] + b0, vacc[mi][ni][3] + b1v);
            }

        // ------------- y = v @ WpT (BwA) -------------
        float yacc[2][4][4];
        ZERO_ACC(yacc);
        cp_wait<1>();                 // Wp done (W1(0) may pend)
        __syncthreads();              // Vb published; BwA visible
        mma_gemm128(Vb, BwA, yacc, wm, wn, lane);
        __syncthreads();
        issueB128(BwA, g_W2T, HIDN, tid); cp_commit();   // W2(0) -> BwA

        // ------------- y epilogue: bias into regs, y -> global ------------
        #pragma unroll
        for (int mi = 0; mi < 2; mi++)
            #pragma unroll
            for (int ni = 0; ni < 4; ni++) {
                int r0 = wm * 32 + mi * 16 + gid;
                int cb = wn * 32 + ni * 8 + tig * 2;
                float bb0 = bp[cb], bb1 = bp[cb + 1];
                yacc[mi][ni][0] += bb0;  yacc[mi][ni][1] += bb1;
                yacc[mi][ni][2] += bb0;  yacc[mi][ni][3] += bb1;
                float2 z0 = make_float2(yacc[mi][ni][0], yacc[mi][ni][1]);
                float2 z1 = make_float2(yacc[mi][ni][2], yacc[mi][ni][3]);
                *(float2*)(out + (tile0 + r0) * DD + cb)     = z0;
                *(float2*)(out + (tile0 + r0 + 8) * DD + cb) = z1;
            }

        // LN(y) stats from fragments: intra-group shfl + cross-warp psum
        #pragma unroll
        for (int mi = 0; mi < 2; mi++) {
            float s0 = 0.f, q0 = 0.f, s1 = 0.f, q1 = 0.f;
            #pragma unroll
            for (int ni = 0; ni < 4; ni++) {
                float a = yacc[mi][ni][0], b = yacc[mi][ni][1];
                float c = yacc[mi][ni][2], d = yacc[mi][ni][3];
                s0 += a + b;  q0 += a * a + b * b;
                s1 += c + d;  q1 += c * c + d * d;
            }
            #pragma unroll
            for (int o = 1; o <= 2; o <<= 1) {
                s0 += __shfl_xor_sync(0xffffffffu, s0, o);
                q0 += __shfl_xor_sync(0xffffffffu, q0, o);
                s1 += __shfl_xor_sync(0xffffffffu, s1, o);
                q1 += __shfl_xor_sync(0xffffffffu, q1, o);
            }
            if (tig == 0) {
                int row = wm * 32 + mi * 16 + gid;
                psum[wn * 64 + row]     = s0;  psq[wn * 64 + row]     = q0;
                psum[wn * 64 + row + 8] = s1;  psq[wn * 64 + row + 8] = q1;
            }
        }
        __syncthreads();

        // lny = (y-m)*rs*g2+b2 -> Vb (fp16), from registers
        #pragma unroll
        for (int mi = 0; mi < 2; mi++) {
            int rA = wm * 32 + mi * 16 + gid;
            int rB = rA + 8;
            float mA = (psum[rA] + psum[64 + rA] + psum[128 + rA] + psum[192 + rA]) * (1.f / 128.f);
            float vA = (psq [rA] + psq [64 + rA] + psq [128 + rA] + psq [192 + rA]) * (1.f / 128.f) - mA * mA;
            float mB = (psum[rB] + psum[64 + rB] + psum[128 + rB] + psum[192 + rB]) * (1.f / 128.f);
            float vB = (psq [rB] + psq [64 + rB] + psq [128 + rB] + psq [192 + rB]) * (1.f / 128.f) - mB * mB;
            float rsA = rsqrtf(vA + EPSV), rsB = rsqrtf(vB + EPSV);
            #pragma unroll
            for (int ni = 0; ni < 4; ni++) {
                int cb = wn * 32 + ni * 8 + tig * 2;
                float gg0 = g2[cb], gg1 = g2[cb + 1];
                float bb0 = b2[cb], bb1 = b2[cb + 1];
                *(__half2*)(Vb + rA * VSTR + cb) = __floats2half2_rn(
                    fmaf((yacc[mi][ni][0] - mA) * rsA, gg0, bb0),
                    fmaf((yacc[mi][ni][1] - mA) * rsA, gg1, bb1));
                *(__half2*)(Vb + rB * VSTR + cb) = __floats2half2_rn(
                    fmaf((yacc[mi][ni][2] - mB) * rsB, gg0, bb0),
                    fmaf((yacc[mi][ni][3] - mB) * rsB, gg1, bb1));
            }
        }
        // yacc dead from here (y lives in global)

        // ---------------- MLP: 4 hidden tiles, BwB/BwA ping-pong ----------
        float uacc[2][4][4];
        ZERO_ACC(uacc);
        #pragma unroll 1
        for (int cc = 0; cc < 4; cc++) {
            cp_wait<1>();            // W1(cc) in BwB done
            __syncthreads();         // lny/Gb published; BwB visible
            float tacc[2][4][4];
            ZERO_ACC(tacc);
            mma_gemm128(Vb, BwB, tacc, wm, wn, lane);
            __syncthreads();
            if (cc < 3) {
                issueB128(BwB, g_W1T + (cc + 1) * 128 * DD, DD, tid);
                cp_commit();
            }

            // gelu epilogue -> Gb
            #pragma unroll
            for (int mi = 0; mi < 2; mi++)
                #pragma unroll
                for (int ni = 0; ni < 4; ni++) {
                    int r0 = wm * 32 + mi * 16 + gid;
                    int cb = wn * 32 + ni * 8 + tig * 2;
                    float bb0 = bm1[cc * 128 + cb], bb1 = bm1[cc * 128 + cb + 1];
                    *(__half2*)(Gb + r0 * VSTR + cb) = __floats2half2_rn(
                        gelu_f(tacc[mi][ni][0] + bb0),
                        gelu_f(tacc[mi][ni][1] + bb1));
                    *(__half2*)(Gb + (r0 + 8) * VSTR + cb) = __floats2half2_rn(
                        gelu_f(tacc[mi][ni][2] + bb0),
                        gelu_f(tacc[mi][ni][3] + bb1));
                }
            if (cc < 3) cp_wait<1>(); else cp_wait<0>();   // W2(cc) in BwA done
            __syncthreads();         // Gb published; BwA visible
            mma_gemm128(Gb, BwA, uacc, wm, wn, lane);
            __syncthreads();
            if (cc < 3) {
                issueB128(BwA, g_W2T + (cc + 1) * 128, HIDN, tid);
                cp_commit();
            }
        }

        // -------- z = y(reload from out) + u + bm2 -> out -----------------
        #pragma unroll
        for (int mi = 0; mi < 2; mi++)
            #pragma unroll
            for (int ni = 0; ni < 4; ni++) {
                int r0 = wm * 32 + mi * 16 + gid;
                int cb = wn * 32 + ni * 8 + tig * 2;
                float bb0 = bm2[cb], bb1 = bm2[cb + 1];
                float2 ya = *(float2*)(out + (tile0 + r0) * DD + cb);
                float2 yb = *(float2*)(out + (tile0 + r0 + 8) * DD + cb);
                float2 z0, z1;
                z0.x = ya.x + uacc[mi][ni][0] + bb0;
                z0.y = ya.y + uacc[mi][ni][1] + bb1;
                z1.x = yb.x + uacc[mi][ni][2] + bb0;
                z1.y = yb.y + uacc[mi][ni][3] + bb1;
                *(float2*)(out + (tile0 + r0) * DD + cb)     = z0;
                *(float2*)(out + (tile0 + r0 + 8) * DD + cb) = z1;
            }
    }
}

// ------------------------------ launcher ----------------------------------
extern "C" void kernel_launch(void* const* d_in, const int* in_sizes, int n_in,
                              void* d_out, int out_size)
{
    const float* x   = (const float*)d_in[0];
    const float* g1  = (const float*)d_in[1];
    const float* b1  = (const float*)d_in[2];
    // d_in[3]=Wq, d_in[4]=bq, d_in[7]=rpb : dead
    const float* Wkv = (const float*)d_in[5];
    const float* bkv = (const float*)d_in[6];
    const float* Wp  = (const float*)d_in[8];
    const float* bp  = (const float*)d_in[9];
    const float* g2  = (const float*)d_in[10];
    const float* b2  = (const float*)d_in[11];
    const float* W1  = (const float*)d_in[12];
    const float* bm1 = (const float*)d_in[13];
    const float* W2  = (const float*)d_in[14];
    const float* bm2 = (const float*)d_in[15];
    float* out = (float*)d_out;

    cudaFuncSetAttribute(fused_mma,
                         cudaFuncAttributeMaxDynamicSharedMemorySize,
                         SMEM_BYTES);

    prep_all<<<192, dim3(32, 8)>>>(Wkv, Wp, W1, W2);   // also resets g_ctr

    const int tokens = in_sizes[0] / CC;   // 65536
    const int ntiles = tokens / MT;        // 1024
    fused_mma<<<PGRID, NTHR, SMEM_BYTES>>>(
        x, g1, b1, bkv, bp, g2, b2, bm1, bm2, out, ntiles);
}

// round 12
// speedup vs baseline: 1.1746x; 1.0111x over previous
#include <cuda_runtime.h>
#include <cuda_fp16.h>
#include <math.h>
#include <stdint.h>

// ===========================================================================
// Live math (softmax over size-1 axis == 1 kills q/Wq/bq/rpb/k-half of Wkv):
//   h = LN(x;g1,b1); v = h@Wv+bv; y = v@Wp+bp;
//   z = y + gelu(LN(y;g2,b2)@W1+bm1)@W2 + bm2
// mma.sync m16n8k16 fp16 (fp32 accum), ldmatrix, persistent CTAs.
// R12: stage-2 as 3 x K=128 chunks on the BwA/BwB ping-pong; MLP loop at
// 2 barriers/iter; short-chain sigmoid-form tanh gelu (1 exp + 1 rcp).
// ===========================================================================

#define CC    384
#define DD    128
#define HIDN  512
#define MT    64
#define NTHR  256
#define EPSV  1e-5f
#define PGRID 304    // persistent CTAs (2 per SM, 152 SMs)

#define WSTR  136    // K=128 tile stride (halves); row step 272B -> ldsm-clean
#define VSTR  136

// smem byte offsets
#define OFF_BB   0          // 2 x (128x136) fp16 = 69632
#define OFF_VB   69632      // v / lny : 64 x 136 fp16 = 17408
#define OFF_GB   87040      // gelu / stage-2 A chunk : 64 x 136 fp16 = 17408
#define OFF_PSUM 104448     // 256 fp32
#define OFF_PSQ  105472     // 256 fp32
#define OFF_MEAN 106496     // 64 fp32
#define OFF_RSTD 106752     // 64 fp32
#define OFF_CTR  107008
#define SMEM_BYTES 107136

// Pre-transposed fp16 weights, [n][k] row-major (mma row.col B operand)
__device__ __half g_WvT[DD * CC];
__device__ __half g_WpT[DD * DD];
__device__ __half g_W1T[HIDN * DD];
__device__ __half g_W2T[DD * HIDN];
__device__ int    g_ctr;

__device__ __forceinline__ uint32_t smem_u32(const void* p) {
    uint32_t a;
    asm("{ .reg .u64 t; cvta.to.shared.u64 t, %1; cvt.u32.u64 %0, t; }"
        : "=r"(a) : "l"(p));
    return a;
}
__device__ __forceinline__ void cp16(uint32_t dst, const void* src) {
    asm volatile("cp.async.cg.shared.global [%0], [%1], 16;"
                 :: "r"(dst), "l"(src));
}
__device__ __forceinline__ void cp_commit() {
    asm volatile("cp.async.commit_group;" ::: "memory");
}
template<int N> __device__ __forceinline__ void cp_wait() {
    asm volatile("cp.async.wait_group %0;" :: "n"(N) : "memory");
}
__device__ __forceinline__ void ldsm4(uint32_t r[4], uint32_t addr) {
    asm volatile("ldmatrix.sync.aligned.m8n8.x4.shared.b16 {%0,%1,%2,%3}, [%4];"
                 : "=r"(r[0]), "=r"(r[1]), "=r"(r[2]), "=r"(r[3]) : "r"(addr));
}
__device__ __forceinline__ void mma16(float c[4],
    uint32_t a0, uint32_t a1, uint32_t a2, uint32_t a3,
    uint32_t b0, uint32_t b1) {
    asm volatile(
        "mma.sync.aligned.m16n8k16.row.col.f32.f16.f16.f32 "
        "{%0,%1,%2,%3}, {%4,%5,%6,%7}, {%8,%9}, {%0,%1,%2,%3};"
        : "+f"(c[0]), "+f"(c[1]), "+f"(c[2]), "+f"(c[3])
        : "r"(a0), "r"(a1), "r"(a2), "r"(a3), "r"(b0), "r"(b1));
}

// Tanh-form gelu via sigmoid: gelu(v) = v / (1 + exp(v*(-c1 - c2*v^2))).
// Short dep chain: mul, fma, mul+EX2, add, RCP+mul. Deviation from exact
// erf-gelu < 2e-5 for |v| <~ 1.5 (actual t std ~0.23).
__device__ __forceinline__ float gelu_f(float v) {
    float v2 = v * v;
    float a  = fmaf(-0.0713548162726f, v2, -1.5957691216057f);
    float e  = __expf(v * a);
    return __fdividef(v, 1.f + e);
}

// ----- MMA body -----------------------------------------------------------
#define MMA_KSTEP(acc, aA0, aA1, aB0, aB1, koff) { \
    uint32_t a0[4], a1[4], b0[4], b1[4]; \
    ldsm4(a0, (aA0) + (koff)); ldsm4(a1, (aA1) + (koff)); \
    ldsm4(b0, (aB0) + (koff)); ldsm4(b1, (aB1) + (koff)); \
    mma16(acc[0][0], a0[0],a0[1],a0[2],a0[3], b0[0], b0[2]); \
    mma16(acc[0][1], a0[0],a0[1],a0[2],a0[3], b0[1], b0[3]); \
    mma16(acc[0][2], a0[0],a0[1],a0[2],a0[3], b1[0], b1[2]); \
    mma16(acc[0][3], a0[0],a0[1],a0[2],a0[3], b1[1], b1[3]); \
    mma16(acc[1][0], a1[0],a1[1],a1[2],a1[3], b0[0], b0[2]); \
    mma16(acc[1][1], a1[0],a1[1],a1[2],a1[3], b0[1], b0[3]); \
    mma16(acc[1][2], a1[0],a1[1],a1[2],a1[3], b1[0], b1[2]); \
    mma16(acc[1][3], a1[0],a1[1],a1[2],a1[3], b1[1], b1[3]); \
}

// K=128 GEMM: A stride VSTR, B stride WSTR
__device__ __forceinline__ void mma_gemm128(
    const __half* As, const __half* Bs,
    float acc[2][4][4], int wm, int wn, int lane)
{
    const int lrow = lane & 15;
    const int lcol = (lane >> 4) << 3;
    uint32_t aA0 = smem_u32(As + (wm * 32 +      lrow) * VSTR + lcol);
    uint32_t aA1 = smem_u32(As + (wm * 32 + 16 + lrow) * VSTR + lcol);
    uint32_t aB0 = smem_u32(Bs + (wn * 32 +      lrow) * WSTR + lcol);
    uint32_t aB1 = smem_u32(Bs + (wn * 32 + 16 + lrow) * WSTR + lcol);
    #pragma unroll
    for (int k0 = 0; k0 < 128; k0 += 16)
        MMA_KSTEP(acc, aA0, aA1, aB0, aB1, k0 * 2);
}

// ----- async B loader: 128 rows x 128 halves of Wg[n][ldw] ----------------
__device__ __forceinline__ void issueB128(__half* Bdst, const __half* __restrict__ Wg,
                                          int ldw, int tid)
{
    #pragma unroll
    for (int i = 0; i < 8; i++) {
        int idx = tid + NTHR * i;
        int row = idx >> 4;
        int g8  = (idx & 15) << 3;
        cp16(smem_u32(Bdst + row * WSTR + g8), Wg + row * ldw + g8);
    }
}

#define ZERO_ACC(A) { _Pragma("unroll") for (int _m=0;_m<2;_m++) \
    _Pragma("unroll") for (int _n=0;_n<4;_n++) \
    _Pragma("unroll") for (int _q=0;_q<4;_q++) (A)[_m][_n][_q] = 0.f; }

// ---------------- merged weight-prep (one launch) + counter reset ---------
__global__ void prep_all(const float* __restrict__ Wkv,
                         const float* __restrict__ Wp_,
                         const float* __restrict__ W1,
                         const float* __restrict__ W2)
{
    if (blockIdx.x == 0 && threadIdx.x == 0 && threadIdx.y == 0)
        g_ctr = 0;

    const float* src; __half* dst;
    int K, lds, coloff, kb, nb;
    int b = blockIdx.x;
    if (b < 48)       { src = Wkv; dst = g_WvT; K = CC;   lds = 256;  coloff = 128;
                        kb = b % 12;        nb = b / 12; }
    else if (b < 64)  { int i = b - 48;  src = Wp_; dst = g_WpT; K = DD;   lds = DD;
                        coloff = 0; kb = i % 4;  nb = i / 4; }
    else if (b < 128) { int i = b - 64;  src = W1;  dst = g_W1T; K = DD;   lds = HIDN;
                        coloff = 0; kb = i % 4;  nb = i / 4; }
    else              { int i = b - 128; src = W2;  dst = g_W2T; K = HIDN; lds = DD;
                        coloff = 0; kb = i % 16; nb = i / 16; }

    __shared__ float tile[32][33];
    int k0 = kb * 32, n0 = nb * 32;
    int tx = threadIdx.x, ty = threadIdx.y;
    #pragma unroll
    for (int j = 0; j < 4; j++)
        tile[ty + 8 * j][tx] = src[(k0 + ty + 8 * j) * lds + coloff + n0 + tx];
    __syncthreads();
    #pragma unroll
    for (int j = 0; j < 4; j++)
        dst[(n0 + ty + 8 * j) * K + k0 + tx] =
            __float2half_rn(tile[tx][ty + 8 * j]);
}

// ------------------------------ main kernel -------------------------------
extern __shared__ char smem_raw[];

__global__ void __launch_bounds__(NTHR, 2) fused_mma(
    const float* __restrict__ x,
    const float* __restrict__ g1, const float* __restrict__ b1,
    const float* __restrict__ bkv, const float* __restrict__ bp,
    const float* __restrict__ g2, const float* __restrict__ b2,
    const float* __restrict__ bm1, const float* __restrict__ bm2,
    float* __restrict__ out, int ntiles)
{
    __half* BwA = (__half*)(smem_raw + OFF_BB);
    __half* BwB = BwA + 128 * WSTR;
    __half* Vb  = (__half*)(smem_raw + OFF_VB);
    __half* Gb  = (__half*)(smem_raw + OFF_GB);
    __half* Ab  = (__half*)(smem_raw + OFF_GB);  // stage-2 A chunk alias
    float* psum  = (float*)(smem_raw + OFF_PSUM);
    float* psq   = (float*)(smem_raw + OFF_PSQ);
    float* smean = (float*)(smem_raw + OFF_MEAN);
    float* srstd = (float*)(smem_raw + OFF_RSTD);
    volatile int* stile = (volatile int*)(smem_raw + OFF_CTR);

    const int tid  = threadIdx.x;
    const int lane = tid & 31;
    const int warp = tid >> 5;
    const int wm   = warp >> 2;
    const int wn   = warp & 3;
    const int gid  = lane >> 2;
    const int tig  = lane & 3;

    for (;;) {
        if (tid == 0) *stile = atomicAdd(&g_ctr, 1);
        __syncthreads();             // broadcast; all smem free for reuse
        int t = *stile;
        if (t >= ntiles) break;
        const long tile0 = (long)t * MT;

        // Prefetch Wv chunk0 -> BwA (hides under LN stats)
        issueB128(BwA, g_WvT, CC, tid); cp_commit();

        // ---------------- LN(x) stats ----------------
        #pragma unroll 1
        for (int i = 0; i < 8; i++) {
            int row = warp * 8 + i;
            const float* xr = x + (tile0 + row) * CC;
            float s = 0.f, ss = 0.f;
            #pragma unroll
            for (int u = 0; u < 12; u++) {
                float tv = xr[lane + 32 * u];
                s += tv; ss += tv * tv;
            }
            #pragma unroll
            for (int o = 16; o > 0; o >>= 1) {
                s  += __shfl_xor_sync(0xffffffffu, s,  o);
                ss += __shfl_xor_sync(0xffffffffu, ss, o);
            }
            if (lane == 0) {
                float m = s * (1.f / 384.f);
                float v = ss * (1.f / 384.f) - m * m;
                smean[row] = m;
                srstd[row] = rsqrtf(v + EPSV);
            }
        }
        __syncthreads();

        // -------- v = LN(x) @ WvT : 3 x K=128 chunks, BwA/BwB ping-pong ---
        float vacc[2][4][4];
        ZERO_ACC(vacc);
        #pragma unroll 1
        for (int c = 0; c < 3; c++) {
            __half* Bcur = (c & 1) ? BwB : BwA;
            if (c == 0)      { issueB128(BwB, g_WvT + 128, CC, tid); cp_commit(); }
            else if (c == 1) { issueB128(BwA, g_WvT + 256, CC, tid); cp_commit(); }
            else             { issueB128(BwB, g_WpT, DD, tid);       cp_commit(); }

            // fill A chunk: normalize x[:, kc..kc+127] -> fp16
            int kc = c * 128;
            #pragma unroll
            for (int i = 0; i < 8; i++) {
                int idx = tid + NTHR * i;        // 64 rows x 32 quads
                int row = idx >> 5, q = (idx & 31) * 4;
                int k = kc + q;
                float4 xx = *(const float4*)(x + (tile0 + row) * CC + k);
                float4 gg = *(const float4*)(g1 + k);
                float4 bb = *(const float4*)(b1 + k);
                float m = smean[row], rs = srstd[row];
                __half2 h0 = __floats2half2_rn(fmaf((xx.x - m) * rs, gg.x, bb.x),
                                               fmaf((xx.y - m) * rs, gg.y, bb.y));
                __half2 h1 = __floats2half2_rn(fmaf((xx.z - m) * rs, gg.z, bb.z),
                                               fmaf((xx.w - m) * rs, gg.w, bb.w));
                uint2 pk = make_uint2(*(uint32_t*)&h0, *(uint32_t*)&h1);
                *(uint2*)(Ab + row * VSTR + q) = pk;
            }
            cp_wait<1>();
            __syncthreads();         // chunk-c B ready; Ab published
            mma_gemm128(Ab, Bcur, vacc, wm, wn, lane);
            __syncthreads();         // all past gemm: next refills are safe
        }

        // W1(0) -> BwA (BwA free after stage-2 final sync)
        issueB128(BwA, g_W1T, DD, tid); cp_commit();

        // v epilogue -> Vb (fp16)
        #pragma unroll
        for (int mi = 0; mi < 2; mi++)
            #pragma unroll
            for (int ni = 0; ni < 4; ni++) {
                int r0 = wm * 32 + mi * 16 + gid;
                int cb = wn * 32 + ni * 8 + tig * 2;
                float b0 = bkv[128 + cb], b1v = bkv[129 + cb];
                *(__half2*)(Vb + r0 * VSTR + cb) =
                    __floats2half2_rn(vacc[mi][ni][0] + b0, vacc[mi][ni][1] + b1v);
                *(__half2*)(Vb + (r0 + 8) * VSTR + cb) =
                    __floats2half2_rn(vacc[mi][ni][2] + b0, vacc[mi][ni][3] + b1v);
            }

        // ------------- y = v @ WpT (BwB) -------------
        float yacc[2][4][4];
        ZERO_ACC(yacc);
        cp_wait<1>();                // Wp done (W1(0) may pend)
        __syncthreads();             // Vb published; BwB visible
        mma_gemm128(Vb, BwB, yacc, wm, wn, lane);

        // y epilogue: bias in regs, y -> global, LN(y) stats via shfl
        #pragma unroll
        for (int mi = 0; mi < 2; mi++)
            #pragma unroll
            for (int ni = 0; ni < 4; ni++) {
                int r0 = wm * 32 + mi * 16 + gid;
                int cb = wn * 32 + ni * 8 + tig * 2;
                float bb0 = bp[cb], bb1 = bp[cb + 1];
                yacc[mi][ni][0] += bb0;  yacc[mi][ni][1] += bb1;
                yacc[mi][ni][2] += bb0;  yacc[mi][ni][3] += bb1;
                float2 z0 = make_float2(yacc[mi][ni][0], yacc[mi][ni][1]);
                float2 z1 = make_float2(yacc[mi][ni][2], yacc[mi][ni][3]);
                *(float2*)(out + (tile0 + r0) * DD + cb)     = z0;
                *(float2*)(out + (tile0 + r0 + 8) * DD + cb) = z1;
            }
        #pragma unroll
        for (int mi = 0; mi < 2; mi++) {
            float s0 = 0.f, q0 = 0.f, s1 = 0.f, q1 = 0.f;
            #pragma unroll
            for (int ni = 0; ni < 4; ni++) {
                float a = yacc[mi][ni][0], b = yacc[mi][ni][1];
                float c = yacc[mi][ni][2], d = yacc[mi][ni][3];
                s0 += a + b;  q0 += a * a + b * b;
                s1 += c + d;  q1 += c * c + d * d;
            }
            #pragma unroll
            for (int o = 1; o <= 2; o <<= 1) {
                s0 += __shfl_xor_sync(0xffffffffu, s0, o);
                q0 += __shfl_xor_sync(0xffffffffu, q0, o);
                s1 += __shfl_xor_sync(0xffffffffu, s1, o);
                q1 += __shfl_xor_sync(0xffffffffu, q1, o);
            }
            if (tig == 0) {
                int row = wm * 32 + mi * 16 + gid;
                psum[wn * 64 + row]     = s0;  psq[wn * 64 + row]     = q0;
                psum[wn * 64 + row + 8] = s1;  psq[wn * 64 + row + 8] = q1;
            }
        }
        __syncthreads();             // psum ready; all past y gemm (BwB free)

        // lny -> Vb (fp16) from registers
        #pragma unroll
        for (int mi = 0; mi < 2; mi++) {
            int rA = wm * 32 + mi * 16 + gid;
            int rB = rA + 8;
            float mA = (psum[rA] + psum[64 + rA] + psum[128 + rA] + psum[192 + rA]) * (1.f / 128.f);
            float vA = (psq [rA] + psq [64 + rA] + psq [128 + rA] + psq [192 + rA]) * (1.f / 128.f) - mA * mA;
            float mB = (psum[rB] + psum[64 + rB] + psum[128 + rB] + psum[192 + rB]) * (1.f / 128.f);
            float vB = (psq [rB] + psq [64 + rB] + psq [128 + rB] + psq [192 + rB]) * (1.f / 128.f) - mB * mB;
            float rsA = rsqrtf(vA + EPSV), rsB = rsqrtf(vB + EPSV);
            #pragma unroll
            for (int ni = 0; ni < 4; ni++) {
                int cb = wn * 32 + ni * 8 + tig * 2;
                float gg0 = g2[cb], gg1 = g2[cb + 1];
                float bb0 = b2[cb], bb1 = b2[cb + 1];
                *(__half2*)(Vb + rA * VSTR + cb) = __floats2half2_rn(
                    fmaf((yacc[mi][ni][0] - mA) * rsA, gg0, bb0),
                    fmaf((yacc[mi][ni][1] - mA) * rsA, gg1, bb1));
                *(__half2*)(Vb + rB * VSTR + cb) = __floats2half2_rn(
                    fmaf((yacc[mi][ni][2] - mB) * rsB, gg0, bb0),
                    fmaf((yacc[mi][ni][3] - mB) * rsB, gg1, bb1));
            }
        }
        // yacc dead (y lives in global)

        // ---------- MLP: 4 hidden tiles, 2 barriers per iteration ----------
        float uacc[2][4][4];
        ZERO_ACC(uacc);
        #pragma unroll 1
        for (int cc = 0; cc < 4; cc++) {
            cp_wait<0>();            // W1(cc) in BwA done
            __syncthreads();         // Vb/lny & prev Gb-read done; BwB free
            issueB128(BwB, g_W2T + cc * 128, HIDN, tid); cp_commit();
            float tacc[2][4][4];
            ZERO_ACC(tacc);
            mma_gemm128(Vb, BwA, tacc, wm, wn, lane);

            // gelu -> Gb (per-warp-owned regions; no sync needed before)
            #pragma unroll
            for (int mi = 0; mi < 2; mi++)
                #pragma unroll
                for (int ni = 0; ni < 4; ni++) {
                    int r0 = wm * 32 + mi * 16 + gid;
                    int cb = wn * 32 + ni * 8 + tig * 2;
                    float bb0 = bm1[cc * 128 + cb], bb1 = bm1[cc * 128 + cb + 1];
                    *(__half2*)(Gb + r0 * VSTR + cb) = __floats2half2_rn(
                        gelu_f(tacc[mi][ni][0] + bb0),
                        gelu_f(tacc[mi][ni][1] + bb1));
                    *(__half2*)(Gb + (r0 + 8) * VSTR + cb) = __floats2half2_rn(
                        gelu_f(tacc[mi][ni][2] + bb0),
                        gelu_f(tacc[mi][ni][3] + bb1));
                }
            cp_wait<0>();            // W2(cc) in BwB done
            __syncthreads();         // Gb published; all past tacc (BwA free)
            if (cc < 3) {
                issueB128(BwA, g_W1T + (cc + 1) * 128 * DD, DD, tid);
                cp_commit();
            }
            mma_gemm128(Gb, BwB, uacc, wm, wn, lane);
        }

        // -------- z = y(reload, own addresses) + u + bm2 -> out -----------
        #pragma unroll
        for (int mi = 0; mi < 2; mi++)
            #pragma unroll
            for (int ni = 0; ni < 4; ni++) {
                int r0 = wm * 32 + mi * 16 + gid;
                int cb = wn * 32 + ni * 8 + tig * 2;
                float bb0 = bm2[cb], bb1 = bm2[cb + 1];
                float2 ya = *(float2*)(out + (tile0 + r0) * DD + cb);
                float2 yb = *(float2*)(out + (tile0 + r0 + 8) * DD + cb);
                float2 z0, z1;
                z0.x = ya.x + uacc[mi][ni][0] + bb0;
                z0.y = ya.y + uacc[mi][ni][1] + bb1;
                z1.x = yb.x + uacc[mi][ni][2] + bb0;
                z1.y = yb.y + uacc[mi][ni][3] + bb1;
                *(float2*)(out + (tile0 + r0) * DD + cb)     = z0;
                *(float2*)(out + (tile0 + r0 + 8) * DD + cb) = z1;
            }
    }
}

// ------------------------------ launcher ----------------------------------
extern "C" void kernel_launch(void* const* d_in, const int* in_sizes, int n_in,
                              void* d_out, int out_size)
{
    const float* x   = (const float*)d_in[0];
    const float* g1  = (const float*)d_in[1];
    const float* b1  = (const float*)d_in[2];
    // d_in[3]=Wq, d_in[4]=bq, d_in[7]=rpb : dead
    const float* Wkv = (const float*)d_in[5];
    const float* bkv = (const float*)d_in[6];
    const float* Wp  = (const float*)d_in[8];
    const float* bp  = (const float*)d_in[9];
    const float* g2  = (const float*)d_in[10];
    const float* b2  = (const float*)d_in[11];
    const float* W1  = (const float*)d_in[12];
    const float* bm1 = (const float*)d_in[13];
    const float* W2  = (const float*)d_in[14];
    const float* bm2 = (const float*)d_in[15];
    float* out = (float*)d_out;

    cudaFuncSetAttribute(fused_mma,
                         cudaFuncAttributeMaxDynamicSharedMemorySize,
                         SMEM_BYTES);

    prep_all<<<192, dim3(32, 8)>>>(Wkv, Wp, W1, W2);   // also resets g_ctr

    const int tokens = in_sizes[0] / CC;   // 65536
    const int ntiles = tokens / MT;        // 1024
    fused_mma<<<PGRID, NTHR, SMEM_BYTES>>>(
        x, g1, b1, bkv, bp, g2, b2, bm1, bm2, out, ntiles);
}